// round 5
// baseline (speedup 1.0000x reference)
#include <cuda_runtime.h>
#include <cuda_bf16.h>
#include <math.h>
#include <stdint.h>

#define BATCH 4
#define SEQ   2048
#define DIM   1024
#define MROWS (BATCH * SEQ)

// Scratch (__device__ globals; allocation-free rule). All GEMM inputs are
// pre-rounded to tf32 (RNA) in gmem, so GEMM loads can be raw cp.async.
__device__ float g_xr[MROWS * DIM];                // tf32-rounded x
__device__ float g_q[BATCH * SEQ * DIM];           // tf32-rounded
__device__ float g_k[BATCH * SEQ * DIM];           // tf32-rounded
__device__ float g_v[BATCH * SEQ * DIM];           // tf32-rounded
__device__ float g_vt[BATCH * DIM * SEQ];          // V^T [dim][seq]
__device__ float g_wt[3 * DIM * DIM];              // W^T [n][k], tf32-rounded
__device__ float g_sc[(size_t)BATCH * SEQ * SEQ];  // scores -> probs

// GEMM config: CTA tile 128x128x32, 8 warps as 2(M) x 4(N), warp tile 64x32.
#define BM 128
#define BN 128
#define BK 32
#define STAGES 3
#define NTH 256
#define A_STAGE 16384
#define B_STAGE 16384
#define SM_B (STAGES * A_STAGE)
#define SMEM_TOTAL (STAGES * (A_STAGE + B_STAGE))   // 96 KB

// ---------------------------------------------------------------------------
// helpers
// ---------------------------------------------------------------------------
__device__ __forceinline__ float f2tf32(float f) {
    uint32_t u;
    asm("cvt.rna.tf32.f32 %0, %1;" : "=r"(u) : "f"(f));
    return __uint_as_float(u);
}

__device__ __forceinline__ uint32_t smem_u32(const void* p) {
    uint32_t a;
    asm("{ .reg .u64 t; cvta.to.shared.u64 t, %1; cvt.u32.u64 %0, t; }"
        : "=r"(a) : "l"(p));
    return a;
}

__device__ __forceinline__ void cp16(uint32_t dst, const void* src) {
    asm volatile("cp.async.cg.shared.global [%0], [%1], 16;"
                 :: "r"(dst), "l"(src));
}
#define CP_COMMIT() asm volatile("cp.async.commit_group;" ::: "memory")
#define CP_WAIT1()  asm volatile("cp.async.wait_group 1;" ::: "memory")

__device__ __forceinline__ void ldsm4(uint32_t r[4], uint32_t addr) {
    asm volatile("ldmatrix.sync.aligned.m8n8.x4.shared.b16 {%0,%1,%2,%3}, [%4];"
                 : "=r"(r[0]), "=r"(r[1]), "=r"(r[2]), "=r"(r[3]) : "r"(addr));
}

__device__ __forceinline__ void mma_tf32(float c[4], const uint32_t a[4],
                                         uint32_t b0, uint32_t b1) {
    asm volatile(
        "mma.sync.aligned.m16n8k8.row.col.f32.tf32.tf32.f32 "
        "{%0,%1,%2,%3}, {%4,%5,%6,%7}, {%8,%9}, {%0,%1,%2,%3};"
        : "+f"(c[0]), "+f"(c[1]), "+f"(c[2]), "+f"(c[3])
        : "r"(a[0]), "r"(a[1]), "r"(a[2]), "r"(a[3]), "r"(b0), "r"(b1));
}

// ---------------------------------------------------------------------------
// smem layout: k-chunk-major, 16B chunks. chunk (m, c): addr16 = c*128 + (m^c).
// Conflict-free for cp.async stores (lanes vary c at fixed m) and ldmatrix
// phases (8 consecutive m at fixed c).
// ---------------------------------------------------------------------------
__device__ __forceinline__ void issue_stage(const float* __restrict__ Ag, int lda,
                                            const float* __restrict__ Bg, int ldb,
                                            uint32_t sb, int ks, int buf, int tid) {
    const float* a = Ag + (size_t)ks * BK;
    uint32_t ab = sb + buf * A_STAGE;
    #pragma unroll
    for (int t = 0; t < 4; t++) {
        int idx = tid + t * NTH;
        int m = idx >> 3, c = idx & 7;
        cp16(ab + (((c << 7) + (m ^ c)) << 4), a + (size_t)m * lda + (c << 2));
    }
    const float* b = Bg + (size_t)ks * BK;
    uint32_t bb = sb + SM_B + buf * B_STAGE;
    #pragma unroll
    for (int t = 0; t < 4; t++) {
        int idx = tid + t * NTH;
        int n = idx >> 3, c = idx & 7;
        cp16(bb + (((c << 7) + (n ^ c)) << 4), b + (size_t)n * ldb + (c << 2));
    }
}

// Compute one k-stage (BK=32) from smem buffer via ldmatrix + mma.
__device__ __forceinline__ void compute_stage(uint32_t sb, int buf,
                                              float c[4][4][4],
                                              int lane, int warpM, int warpN) {
    const uint32_t ab = sb + buf * A_STAGE;
    const uint32_t bb = sb + SM_B + buf * B_STAGE;
    const int q = lane >> 3, r = lane & 7;
    #pragma unroll
    for (int j = 0; j < 4; j++) {
        const int c0 = 2 * j;
        // A: matrices (rows m..m+7, c), (m+8.., c), (m.., c+1), (m+8.., c+1)
        const int cA = c0 + (q >> 1);
        const int mo = ((q & 1) << 3) + r;
        uint32_t afr[4][4];
        #pragma unroll
        for (int mt = 0; mt < 4; mt++) {
            int m = warpM * 64 + mt * 16 + mo;
            ldsm4(afr[mt], ab + (((cA << 7) + (m ^ cA)) << 4));
        }
        // B: matrices (n..n+7, c), (n.., c+1), (n+8.., c), (n+8.., c+1)
        const int cB = c0 + (q & 1);
        const int no = ((q >> 1) << 3) + r;
        uint32_t bfr[2][4];
        #pragma unroll
        for (int bt = 0; bt < 2; bt++) {
            int n = warpN * 32 + bt * 16 + no;
            ldsm4(bfr[bt], bb + (((cB << 7) + (n ^ cB)) << 4));
        }
        #pragma unroll
        for (int mt = 0; mt < 4; mt++)
            #pragma unroll
            for (int nt = 0; nt < 4; nt++)
                mma_tf32(c[mt][nt], afr[mt],
                         bfr[nt >> 1][(nt & 1) * 2], bfr[nt >> 1][(nt & 1) * 2 + 1]);
    }
}

// ---------------------------------------------------------------------------
// Core: C[128x128] = A[128 x nk*32] @ B^T (B: [128 x nk*32] K-major rows).
// 3-stage cp.async pipeline. ROUND: tf32-round epilogue stores.
// ---------------------------------------------------------------------------
template <bool ROUND>
__device__ __forceinline__ void gemm_core(const float* __restrict__ Ag, int lda,
                                          const float* __restrict__ Bg, int ldb,
                                          float* __restrict__ Cg, int ldc,
                                          int nk, float scale, char* smem) {
    const uint32_t sb = smem_u32(smem);
    const int tid = threadIdx.x, lane = tid & 31, warp = tid >> 5;
    const int warpM = warp >> 2, warpN = warp & 3;

    float c[4][4][4] = {};

    issue_stage(Ag, lda, Bg, ldb, sb, 0, 0, tid);
    CP_COMMIT();
    issue_stage(Ag, lda, Bg, ldb, sb, 1, 1, tid);
    CP_COMMIT();

    for (int ks = 0; ks < nk; ks++) {
        CP_WAIT1();
        __syncthreads();
        if (ks + 2 < nk)
            issue_stage(Ag, lda, Bg, ldb, sb, ks + 2, (ks + 2) % STAGES, tid);
        CP_COMMIT();
        compute_stage(sb, ks % STAGES, c, lane, warpM, warpN);
        __syncthreads();
    }

    // Epilogue
    #pragma unroll
    for (int mt = 0; mt < 4; mt++)
        #pragma unroll
        for (int nt = 0; nt < 4; nt++) {
            int rrow = warpM * 64 + mt * 16 + (lane >> 2);
            int ccol = warpN * 32 + nt * 8 + (lane & 3) * 2;
            float v0 = c[mt][nt][0] * scale, v1 = c[mt][nt][1] * scale;
            float v2 = c[mt][nt][2] * scale, v3 = c[mt][nt][3] * scale;
            if (ROUND) {
                v0 = f2tf32(v0); v1 = f2tf32(v1);
                v2 = f2tf32(v2); v3 = f2tf32(v3);
            }
            *reinterpret_cast<float2*>(&Cg[(size_t)rrow * ldc + ccol]) =
                make_float2(v0, v1);
            *reinterpret_cast<float2*>(&Cg[(size_t)(rrow + 8) * ldc + ccol]) =
                make_float2(v2, v3);
        }
}

// ---------------------------------------------------------------------------
// GEMM kernels
// ---------------------------------------------------------------------------
__global__ __launch_bounds__(NTH, 2)
void mm_qkv(const float* __restrict__ dummy) {
    extern __shared__ char smem[];
    const int which = blockIdx.z;
    const int row0 = blockIdx.y * BM, col0 = blockIdx.x * BN;
    const float* A = g_xr + (size_t)row0 * DIM;
    const float* B = g_wt + (size_t)which * DIM * DIM + (size_t)col0 * DIM;
    float* C = ((which == 0) ? g_q : (which == 1) ? g_k : g_v) +
               (size_t)row0 * DIM + col0;
    gemm_core<true>(A, DIM, B, DIM, C, DIM, DIM / BK, 1.0f, smem);
}

__global__ __launch_bounds__(NTH, 2)
void mm_scores(float scale) {
    const int bx = blockIdx.x, by = blockIdx.y;
    if (bx > by) return;  // fully above diagonal
    extern __shared__ char smem[];
    const int b = blockIdx.z;
    const int row0 = by * BM, col0 = bx * BN;
    const float* A = g_q + (size_t)b * SEQ * DIM + (size_t)row0 * DIM;
    const float* B = g_k + (size_t)b * SEQ * DIM + (size_t)col0 * DIM;
    float* C = g_sc + (size_t)b * SEQ * SEQ + (size_t)row0 * SEQ + col0;
    gemm_core<false>(A, DIM, B, DIM, C, SEQ, DIM / BK, scale, smem);
}

__global__ __launch_bounds__(NTH, 2)
void mm_pv(float* __restrict__ out) {
    extern __shared__ char smem[];
    const int b = blockIdx.z;
    const int row0 = blockIdx.y * BM, col0 = blockIdx.x * BN;
    const float* A = g_sc + (size_t)b * SEQ * SEQ + (size_t)row0 * SEQ;
    const float* B = g_vt + (size_t)b * DIM * SEQ + (size_t)col0 * SEQ;
    float* C = out + (size_t)b * SEQ * DIM + (size_t)row0 * DIM + col0;
    const int nk = (row0 + BM) / BK;  // causal truncation
    gemm_core<false>(A, SEQ, B, SEQ, C, DIM, nk, 1.0f, smem);
}

// ---------------------------------------------------------------------------
// Prep kernels
// ---------------------------------------------------------------------------
__global__ void round_x(const float* __restrict__ x) {
    size_t i = (size_t)(blockIdx.x * blockDim.x + threadIdx.x) * 4;
    float4 v = *reinterpret_cast<const float4*>(x + i);
    v.x = f2tf32(v.x); v.y = f2tf32(v.y); v.z = f2tf32(v.z); v.w = f2tf32(v.w);
    *reinterpret_cast<float4*>(g_xr + i) = v;
}

__global__ void tr_w(const float* __restrict__ Wq, const float* __restrict__ Wk,
                     const float* __restrict__ Wv) {
    __shared__ float t[32][33];
    const int z = blockIdx.z;
    const float* S = (z == 0) ? Wq : (z == 1) ? Wk : Wv;
    float* D = g_wt + (size_t)z * DIM * DIM;
    const int x0 = blockIdx.x * 32, y0 = blockIdx.y * 32;
    const int tx = threadIdx.x, ty = threadIdx.y;
    #pragma unroll
    for (int j = 0; j < 32; j += 8)
        t[ty + j][tx] = S[(size_t)(y0 + ty + j) * DIM + x0 + tx];
    __syncthreads();
    #pragma unroll
    for (int j = 0; j < 32; j += 8)
        D[(size_t)(x0 + ty + j) * DIM + y0 + tx] = f2tf32(t[tx][ty + j]);
}

__global__ void tr_v() {
    __shared__ float t[32][33];
    const int b = blockIdx.z;
    const float* S = g_v + (size_t)b * SEQ * DIM;
    float* D = g_vt + (size_t)b * DIM * SEQ;
    const int x0 = blockIdx.x * 32, y0 = blockIdx.y * 32;
    const int tx = threadIdx.x, ty = threadIdx.y;
    #pragma unroll
    for (int j = 0; j < 32; j += 8)
        t[ty + j][tx] = S[(size_t)(y0 + ty + j) * DIM + x0 + tx];
    __syncthreads();
    #pragma unroll
    for (int j = 0; j < 32; j += 8)
        D[(size_t)(x0 + ty + j) * SEQ + y0 + tx] = t[tx][ty + j];
}

// ---------------------------------------------------------------------------
// Causal softmax: smem row cache, tf32-rounded prob output (matches
// rounding-at-load numerics of the PV GEMM). Zero-fill to own block end.
// ---------------------------------------------------------------------------
__global__ __launch_bounds__(NTH)
void softmax_causal() {
    __shared__ float buf[SEQ];
    __shared__ float red[8];
    const int row = blockIdx.x;
    const int q = row & (SEQ - 1);
    float* __restrict__ p = g_sc + (size_t)row * SEQ;
    const int n = q + 1;
    const int limit = (q & ~127) + 128;
    const int tid = threadIdx.x, lane = tid & 31, warp = tid >> 5;

    float m = -1e30f;
    for (int i = tid; i < n; i += NTH) {
        float v = p[i];
        buf[i] = v;
        m = fmaxf(m, v);
    }
    #pragma unroll
    for (int o = 16; o > 0; o >>= 1) m = fmaxf(m, __shfl_xor_sync(~0u, m, o));
    if (lane == 0) red[warp] = m;
    __syncthreads();
    m = red[lane & 7];
    #pragma unroll
    for (int o = 4; o > 0; o >>= 1) m = fmaxf(m, __shfl_xor_sync(~0u, m, o));

    float sum = 0.0f;
    for (int i = tid; i < n; i += NTH) {
        float e = __expf(buf[i] - m);
        buf[i] = e;
        sum += e;
    }
    #pragma unroll
    for (int o = 16; o > 0; o >>= 1) sum += __shfl_xor_sync(~0u, sum, o);
    __syncthreads();
    if (lane == 0) red[warp] = sum;
    __syncthreads();
    sum = red[lane & 7];
    #pragma unroll
    for (int o = 4; o > 0; o >>= 1) sum += __shfl_xor_sync(~0u, sum, o);
    const float inv = 1.0f / sum;

    for (int i = tid; i < n; i += NTH) p[i] = f2tf32(buf[i] * inv);
    for (int i = n + tid; i < limit; i += NTH) p[i] = 0.0f;
}

// ---------------------------------------------------------------------------
extern "C" void kernel_launch(void* const* d_in, const int* in_sizes, int n_in,
                              void* d_out, int out_size) {
    const float* x  = (const float*)d_in[0];
    const float* Wq = (const float*)d_in[1];
    const float* Wk = (const float*)d_in[2];
    const float* Wv = (const float*)d_in[3];
    float* out = (float*)d_out;

    cudaFuncSetAttribute(mm_qkv, cudaFuncAttributeMaxDynamicSharedMemorySize, SMEM_TOTAL);
    cudaFuncSetAttribute(mm_scores, cudaFuncAttributeMaxDynamicSharedMemorySize, SMEM_TOTAL);
    cudaFuncSetAttribute(mm_pv, cudaFuncAttributeMaxDynamicSharedMemorySize, SMEM_TOTAL);

    // 1) pre-round x; W^T (rounded)
    round_x<<<(MROWS * DIM) / (4 * NTH), NTH>>>(x);
    tr_w<<<dim3(32, 32, 3), dim3(32, 8)>>>(Wq, Wk, Wv);
    // 2) QKV projections
    mm_qkv<<<dim3(DIM / BN, MROWS / BM, 3), NTH, SMEM_TOTAL>>>(x);
    // 3) V^T
    tr_v<<<dim3(DIM / 32, SEQ / 32, BATCH), dim3(32, 8)>>>();
    // 4) scores (lower-triangular tiles)
    const float scale = 1.0f / sqrtf((float)DIM);
    mm_scores<<<dim3(SEQ / BN, SEQ / BM, BATCH), NTH, SMEM_TOTAL>>>(scale);
    // 5) softmax
    softmax_causal<<<BATCH * SEQ, NTH>>>();
    // 6) out = P V
    mm_pv<<<dim3(DIM / BN, SEQ / BM, BATCH), NTH, SMEM_TOTAL>>>(out);
}

// round 6
// speedup vs baseline: 1.0850x; 1.0850x over previous
#include <cuda_runtime.h>
#include <cuda_bf16.h>
#include <math.h>
#include <stdint.h>

#define BATCH 4
#define SEQ   2048
#define DIM   1024
#define MROWS (BATCH * SEQ)

// Scratch (__device__ globals)
__device__ float g_q[BATCH * SEQ * DIM];
__device__ float g_k[BATCH * SEQ * DIM];
__device__ float g_v[BATCH * SEQ * DIM];
__device__ float g_vt[BATCH * DIM * SEQ];          // V^T [dim][seq]
__device__ float g_wt[3 * DIM * DIM];              // W^T [n][k]
__device__ float g_sc[(size_t)BATCH * SEQ * SEQ];  // scores -> probs

// GEMM config: CTA 128x256xBK16; 8 warps as 2(M) x 4(N); warp tile 64x64.
#define BM 128
#define BN 256
#define BK 16
#define NTH 256

// smem rows: BK=16 floats = 4 x 16B chunks, padded to 5 chunks (80 B).
// addr(row, c) = row*80 + ((c + 2*(row&1)) & 3) * 16.
// - STS phase (8 consecutive rows, fixed c): 5r mod 8 cycles all residues -> CF.
// - ldmatrix phase (8 consecutive rows, fixed c): same pattern -> CF.
#define ROWB 80

// ---------------------------------------------------------------------------
// helpers
// ---------------------------------------------------------------------------
__device__ __forceinline__ float f2tf32(float f) {
    uint32_t u;
    asm("cvt.rna.tf32.f32 %0, %1;" : "=r"(u) : "f"(f));
    return __uint_as_float(u);
}

__device__ __forceinline__ uint32_t smem_u32(const void* p) {
    uint32_t a;
    asm("{ .reg .u64 t; cvta.to.shared.u64 t, %1; cvt.u32.u64 %0, t; }"
        : "=r"(a) : "l"(p));
    return a;
}

__device__ __forceinline__ void ldsm4(uint32_t r[4], uint32_t addr) {
    asm volatile("ldmatrix.sync.aligned.m8n8.x4.shared.b16 {%0,%1,%2,%3}, [%4];"
                 : "=r"(r[0]), "=r"(r[1]), "=r"(r[2]), "=r"(r[3]) : "r"(addr));
}

__device__ __forceinline__ void mma_tf32(float c[4], const uint32_t a[4],
                                         uint32_t b0, uint32_t b1) {
    asm volatile(
        "mma.sync.aligned.m16n8k8.row.col.f32.tf32.tf32.f32 "
        "{%0,%1,%2,%3}, {%4,%5,%6,%7}, {%8,%9}, {%0,%1,%2,%3};"
        : "+f"(c[0]), "+f"(c[1]), "+f"(c[2]), "+f"(c[3])
        : "r"(a[0]), "r"(a[1]), "r"(a[2]), "r"(a[3]), "r"(b0), "r"(b1));
}

__device__ __forceinline__ uint32_t swz(int row, int c) {
    return (uint32_t)(row * ROWB) + ((((c) + 2 * (row & 1)) & 3) << 4);
}

// ---------------------------------------------------------------------------
// Core: C[128x256] = A[128 x nk*16] @ B^T; A, B K-major rows in gmem.
// Register prefetch -> STS (tf32-round) -> ldmatrix -> mma.
// ---------------------------------------------------------------------------
__device__ __forceinline__ void gemm_core(const float* __restrict__ Ag, int lda,
                                          const float* __restrict__ Bg, int ldb,
                                          float* __restrict__ Cg, int ldc,
                                          int nk, float scale) {
    __shared__ float As[BM * ROWB / 4];
    __shared__ float Bs[BN * ROWB / 4];
    const uint32_t sa = smem_u32(As), sb = smem_u32(Bs);
    char* const Ab = reinterpret_cast<char*>(As);
    char* const Bb = reinterpret_cast<char*>(Bs);

    const int tid = threadIdx.x, lane = tid & 31, warp = tid >> 5;
    const int warpM = warp >> 2, warpN = warp & 3;

    float c[4][8][4] = {};
    float4 pa[2], pb[4];

    // prefetch stage 0: A chunks (r = idx&127, c = idx>>7), B (r=idx&255, c=idx>>8)
    #pragma unroll
    for (int t = 0; t < 2; t++) {
        int idx = tid + t * NTH;
        pa[t] = *reinterpret_cast<const float4*>(
            Ag + (size_t)(idx & 127) * lda + ((idx >> 7) << 2));
    }
    #pragma unroll
    for (int t = 0; t < 4; t++) {
        int idx = tid + t * NTH;
        pb[t] = *reinterpret_cast<const float4*>(
            Bg + (size_t)(idx & 255) * ldb + ((idx >> 8) << 2));
    }

    for (int i = 0; i < nk; i++) {
        __syncthreads();
        // STS (tf32-rounded)
        #pragma unroll
        for (int t = 0; t < 2; t++) {
            int idx = tid + t * NTH;
            int r = idx & 127, cc = idx >> 7;
            float4 v = pa[t];
            v.x = f2tf32(v.x); v.y = f2tf32(v.y);
            v.z = f2tf32(v.z); v.w = f2tf32(v.w);
            *reinterpret_cast<float4*>(Ab + swz(r, cc)) = v;
        }
        #pragma unroll
        for (int t = 0; t < 4; t++) {
            int idx = tid + t * NTH;
            int r = idx & 255, cc = idx >> 8;
            float4 v = pb[t];
            v.x = f2tf32(v.x); v.y = f2tf32(v.y);
            v.z = f2tf32(v.z); v.w = f2tf32(v.w);
            *reinterpret_cast<float4*>(Bb + swz(r, cc)) = v;
        }
        __syncthreads();
        // prefetch next stage
        if (i + 1 < nk) {
            const int kb = (i + 1) * BK;
            #pragma unroll
            for (int t = 0; t < 2; t++) {
                int idx = tid + t * NTH;
                pa[t] = *reinterpret_cast<const float4*>(
                    Ag + (size_t)(idx & 127) * lda + kb + ((idx >> 7) << 2));
            }
            #pragma unroll
            for (int t = 0; t < 4; t++) {
                int idx = tid + t * NTH;
                pb[t] = *reinterpret_cast<const float4*>(
                    Bg + (size_t)(idx & 255) * ldb + kb + ((idx >> 8) << 2));
            }
        }
        // compute 2 k-steps of 8
        #pragma unroll
        for (int ks = 0; ks < 2; ks++) {
            uint32_t afr[4][4];
            const int arow = warpM * 64 + ((lane >> 3) & 1) * 8 + (lane & 7);
            const int ac = 2 * ks + (lane >> 4);
            #pragma unroll
            for (int mt = 0; mt < 4; mt++)
                ldsm4(afr[mt], sa + swz(arow + mt * 16, ac));
            uint32_t bfr[4][4];
            const int brow = warpN * 64 + (lane >> 4) * 8 + (lane & 7);
            const int bc = 2 * ks + ((lane >> 3) & 1);
            #pragma unroll
            for (int np = 0; np < 4; np++)
                ldsm4(bfr[np], sb + swz(brow + np * 16, bc));
            #pragma unroll
            for (int mt = 0; mt < 4; mt++)
                #pragma unroll
                for (int np = 0; np < 4; np++) {
                    mma_tf32(c[mt][2 * np], afr[mt], bfr[np][0], bfr[np][1]);
                    mma_tf32(c[mt][2 * np + 1], afr[mt], bfr[np][2], bfr[np][3]);
                }
        }
    }

    // Epilogue
    #pragma unroll
    for (int mt = 0; mt < 4; mt++)
        #pragma unroll
        for (int nt = 0; nt < 8; nt++) {
            int r = warpM * 64 + mt * 16 + (lane >> 2);
            int cc = warpN * 64 + nt * 8 + (lane & 3) * 2;
            *reinterpret_cast<float2*>(&Cg[(size_t)r * ldc + cc]) =
                make_float2(c[mt][nt][0] * scale, c[mt][nt][1] * scale);
            *reinterpret_cast<float2*>(&Cg[(size_t)(r + 8) * ldc + cc]) =
                make_float2(c[mt][nt][2] * scale, c[mt][nt][3] * scale);
        }
}

// ---------------------------------------------------------------------------
// GEMM kernels
// ---------------------------------------------------------------------------
__global__ __launch_bounds__(NTH)
void mm_qkv(const float* __restrict__ X) {
    const int which = blockIdx.z;
    const int row0 = blockIdx.y * BM, col0 = blockIdx.x * BN;
    const float* A = X + (size_t)row0 * DIM;
    const float* B = g_wt + (size_t)which * DIM * DIM + (size_t)col0 * DIM;
    float* C = ((which == 0) ? g_q : (which == 1) ? g_k : g_v) +
               (size_t)row0 * DIM + col0;
    gemm_core(A, DIM, B, DIM, C, DIM, DIM / BK, 1.0f);
}

__global__ __launch_bounds__(NTH)
void mm_scores(float scale) {
    const int bx = blockIdx.x, by = blockIdx.y;
    if (2 * bx > by) return;  // fully-masked key tile
    const int b = blockIdx.z;
    const int row0 = by * BM, col0 = bx * BN;
    const float* A = g_q + (size_t)b * SEQ * DIM + (size_t)row0 * DIM;
    const float* B = g_k + (size_t)b * SEQ * DIM + (size_t)col0 * DIM;
    float* C = g_sc + (size_t)b * SEQ * SEQ + (size_t)row0 * SEQ + col0;
    gemm_core(A, DIM, B, DIM, C, SEQ, DIM / BK, scale);
}

__global__ __launch_bounds__(NTH)
void mm_pv(float* __restrict__ out) {
    const int b = blockIdx.z;
    const int row0 = blockIdx.y * BM, col0 = blockIdx.x * BN;
    const float* A = g_sc + (size_t)b * SEQ * SEQ + (size_t)row0 * SEQ;
    const float* B = g_vt + (size_t)b * DIM * SEQ + (size_t)col0 * SEQ;
    float* C = out + (size_t)b * SEQ * DIM + (size_t)row0 * DIM + col0;
    gemm_core(A, SEQ, B, SEQ, C, DIM, (row0 + BM) / BK, 1.0f);
}

// ---------------------------------------------------------------------------
// Transposes
// ---------------------------------------------------------------------------
__global__ void tr_w(const float* __restrict__ Wq, const float* __restrict__ Wk,
                     const float* __restrict__ Wv) {
    __shared__ float t[32][33];
    const int z = blockIdx.z;
    const float* S = (z == 0) ? Wq : (z == 1) ? Wk : Wv;
    float* D = g_wt + (size_t)z * DIM * DIM;
    const int x0 = blockIdx.x * 32, y0 = blockIdx.y * 32;
    const int tx = threadIdx.x, ty = threadIdx.y;
    #pragma unroll
    for (int j = 0; j < 32; j += 8)
        t[ty + j][tx] = S[(size_t)(y0 + ty + j) * DIM + x0 + tx];
    __syncthreads();
    #pragma unroll
    for (int j = 0; j < 32; j += 8)
        D[(size_t)(x0 + ty + j) * DIM + y0 + tx] = t[tx][ty + j];
}

__global__ void tr_v() {
    __shared__ float t[32][33];
    const int b = blockIdx.z;
    const float* S = g_v + (size_t)b * SEQ * DIM;
    float* D = g_vt + (size_t)b * DIM * SEQ;
    const int x0 = blockIdx.x * 32, y0 = blockIdx.y * 32;
    const int tx = threadIdx.x, ty = threadIdx.y;
    #pragma unroll
    for (int j = 0; j < 32; j += 8)
        t[ty + j][tx] = S[(size_t)(y0 + ty + j) * DIM + x0 + tx];
    __syncthreads();
    #pragma unroll
    for (int j = 0; j < 32; j += 8)
        D[(size_t)(x0 + ty + j) * SEQ + y0 + tx] = t[tx][ty + j];
}

// ---------------------------------------------------------------------------
// Causal softmax (smem row cache); zero-fill to own 128-block end.
// ---------------------------------------------------------------------------
__global__ __launch_bounds__(NTH)
void softmax_causal() {
    __shared__ float buf[SEQ];
    __shared__ float red[8];
    const int row = blockIdx.x;
    const int q = row & (SEQ - 1);
    float* __restrict__ p = g_sc + (size_t)row * SEQ;
    const int n = q + 1;
    const int limit = (q & ~127) + 128;
    const int tid = threadIdx.x, lane = tid & 31, warp = tid >> 5;

    float m = -1e30f;
    for (int i = tid; i < n; i += NTH) {
        float v = p[i];
        buf[i] = v;
        m = fmaxf(m, v);
    }
    #pragma unroll
    for (int o = 16; o > 0; o >>= 1) m = fmaxf(m, __shfl_xor_sync(~0u, m, o));
    if (lane == 0) red[warp] = m;
    __syncthreads();
    m = red[lane & 7];
    #pragma unroll
    for (int o = 4; o > 0; o >>= 1) m = fmaxf(m, __shfl_xor_sync(~0u, m, o));

    float sum = 0.0f;
    for (int i = tid; i < n; i += NTH) {
        float e = __expf(buf[i] - m);
        buf[i] = e;
        sum += e;
    }
    #pragma unroll
    for (int o = 16; o > 0; o >>= 1) sum += __shfl_xor_sync(~0u, sum, o);
    __syncthreads();
    if (lane == 0) red[warp] = sum;
    __syncthreads();
    sum = red[lane & 7];
    #pragma unroll
    for (int o = 4; o > 0; o >>= 1) sum += __shfl_xor_sync(~0u, sum, o);
    const float inv = 1.0f / sum;

    for (int i = tid; i < n; i += NTH) p[i] = buf[i] * inv;
    for (int i = n + tid; i < limit; i += NTH) p[i] = 0.0f;
}

// ---------------------------------------------------------------------------
extern "C" void kernel_launch(void* const* d_in, const int* in_sizes, int n_in,
                              void* d_out, int out_size) {
    const float* x  = (const float*)d_in[0];
    const float* Wq = (const float*)d_in[1];
    const float* Wk = (const float*)d_in[2];
    const float* Wv = (const float*)d_in[3];
    float* out = (float*)d_out;

    // 1) W^T
    tr_w<<<dim3(32, 32, 3), dim3(32, 8)>>>(Wq, Wk, Wv);
    // 2) QKV projections
    mm_qkv<<<dim3(DIM / BN, MROWS / BM, 3), NTH>>>(x);
    // 3) V^T
    tr_v<<<dim3(DIM / 32, SEQ / 32, BATCH), dim3(32, 8)>>>();
    // 4) scores (lower-triangular tiles)
    const float scale = 1.0f / sqrtf((float)DIM);
    mm_scores<<<dim3(SEQ / BN, SEQ / BM, BATCH), NTH>>>(scale);
    // 5) softmax
    softmax_causal<<<BATCH * SEQ, NTH>>>();
    // 6) out = P V
    mm_pv<<<dim3(DIM / BN, SEQ / BM, BATCH), NTH>>>(out);
}

// round 7
// speedup vs baseline: 2.0303x; 1.8712x over previous
#include <cuda_runtime.h>
#include <cuda_fp16.h>
#include <math.h>
#include <stdint.h>

#define BATCH 4
#define SEQ   2048
#define DIM   1024
#define MROWS (BATCH * SEQ)

// Scratch (__device__ globals)
__device__ float g_q[BATCH * SEQ * DIM];
__device__ float g_k[BATCH * SEQ * DIM];
__device__ float g_v[BATCH * SEQ * DIM];
__device__ float g_vt[BATCH * DIM * SEQ];          // V^T [dim][seq]
__device__ float g_wt[3 * DIM * DIM];              // W^T [n][k]
__device__ float g_sc[(size_t)BATCH * SEQ * SEQ];  // scores -> probs

// GEMM config: CTA 128x256xBK16; 8 warps as 2(M) x 4(N); warp tile 64x64.
#define BM 128
#define BN 256
#define BK 16
#define NTH 256

// fp16 smem rows: BK=16 halves = 32 B = 2 x 16B chunks.
// byte addr(row, chunk) = row*32 + (chunk ^ ((row>>2)&1))*16.
// 16B-group (mod 8) = (2r + c^((r>>2)&1)) mod 8 -> distinct over any 8
// consecutive rows at fixed c (ldmatrix phase) and over the STS phases.
__device__ __forceinline__ uint32_t swz(int row, int chunk) {
    return (uint32_t)(row * 32) + ((uint32_t)(chunk ^ ((row >> 2) & 1)) << 4);
}

// ---------------------------------------------------------------------------
// helpers
// ---------------------------------------------------------------------------
__device__ __forceinline__ uint32_t smem_u32(const void* p) {
    uint32_t a;
    asm("{ .reg .u64 t; cvta.to.shared.u64 t, %1; cvt.u32.u64 %0, t; }"
        : "=r"(a) : "l"(p));
    return a;
}

__device__ __forceinline__ void ldsm4(uint32_t r[4], uint32_t addr) {
    asm volatile("ldmatrix.sync.aligned.m8n8.x4.shared.b16 {%0,%1,%2,%3}, [%4];"
                 : "=r"(r[0]), "=r"(r[1]), "=r"(r[2]), "=r"(r[3]) : "r"(addr));
}

__device__ __forceinline__ void mma_f16(float c[4], const uint32_t a[4],
                                        uint32_t b0, uint32_t b1) {
    asm volatile(
        "mma.sync.aligned.m16n8k16.row.col.f32.f16.f16.f32 "
        "{%0,%1,%2,%3}, {%4,%5,%6,%7}, {%8,%9}, {%0,%1,%2,%3};"
        : "+f"(c[0]), "+f"(c[1]), "+f"(c[2]), "+f"(c[3])
        : "r"(a[0]), "r"(a[1]), "r"(a[2]), "r"(a[3]), "r"(b0), "r"(b1));
}

// Convert float4 (4 consecutive k) -> 4 halves packed in uint2.
__device__ __forceinline__ uint2 pack_h4(float4 v) {
    half2 h01 = __floats2half2_rn(v.x, v.y);
    half2 h23 = __floats2half2_rn(v.z, v.w);
    uint2 r;
    r.x = *reinterpret_cast<uint32_t*>(&h01);
    r.y = *reinterpret_cast<uint32_t*>(&h23);
    return r;
}

// ---------------------------------------------------------------------------
// Core: C[128x256] = A[128 x nk*16] @ B^T; A, B K-major fp32 rows in gmem.
// Register prefetch -> fp16 STS -> ldmatrix.x4 -> mma m16n8k16.
// ---------------------------------------------------------------------------
__device__ __forceinline__ void gemm_core(const float* __restrict__ Ag, int lda,
                                          const float* __restrict__ Bg, int ldb,
                                          float* __restrict__ Cg, int ldc,
                                          int nk, float scale) {
    __shared__ uint32_t As[BM * 32 / 4];   // 4 KB
    __shared__ uint32_t Bs[BN * 32 / 4];   // 8 KB
    const uint32_t sa = smem_u32(As), sb = smem_u32(Bs);
    char* const Ab = reinterpret_cast<char*>(As);
    char* const Bb = reinterpret_cast<char*>(Bs);

    const int tid = threadIdx.x, lane = tid & 31, warp = tid >> 5;
    const int warpM = warp >> 2, warpN = warp & 3;
    const int l15 = lane & 15, lh = lane >> 4;

    float c[4][8][4] = {};
    float4 pa[2], pb[4];

    // prefetch stage 0: idx -> (row = idx>>2, quad = idx&3) of 4 floats
    #pragma unroll
    for (int t = 0; t < 2; t++) {
        int idx = tid + t * NTH;
        pa[t] = *reinterpret_cast<const float4*>(
            Ag + (size_t)(idx >> 2) * lda + ((idx & 3) << 2));
    }
    #pragma unroll
    for (int t = 0; t < 4; t++) {
        int idx = tid + t * NTH;
        pb[t] = *reinterpret_cast<const float4*>(
            Bg + (size_t)(idx >> 2) * ldb + ((idx & 3) << 2));
    }

    for (int i = 0; i < nk; i++) {
        __syncthreads();
        // STS: fp32 -> fp16, 8 B per thread-quad
        #pragma unroll
        for (int t = 0; t < 2; t++) {
            int idx = tid + t * NTH;
            int r = idx >> 2, qd = idx & 3;
            *reinterpret_cast<uint2*>(Ab + swz(r, qd >> 1) + ((qd & 1) << 3)) =
                pack_h4(pa[t]);
        }
        #pragma unroll
        for (int t = 0; t < 4; t++) {
            int idx = tid + t * NTH;
            int r = idx >> 2, qd = idx & 3;
            *reinterpret_cast<uint2*>(Bb + swz(r, qd >> 1) + ((qd & 1) << 3)) =
                pack_h4(pb[t]);
        }
        __syncthreads();
        // prefetch next
        if (i + 1 < nk) {
            const int kb = (i + 1) * BK;
            #pragma unroll
            for (int t = 0; t < 2; t++) {
                int idx = tid + t * NTH;
                pa[t] = *reinterpret_cast<const float4*>(
                    Ag + (size_t)(idx >> 2) * lda + kb + ((idx & 3) << 2));
            }
            #pragma unroll
            for (int t = 0; t < 4; t++) {
                int idx = tid + t * NTH;
                pb[t] = *reinterpret_cast<const float4*>(
                    Bg + (size_t)(idx >> 2) * ldb + kb + ((idx & 3) << 2));
            }
        }
        // fragments: addr lane l -> row base + (l&15), chunk = l>>4
        uint32_t afr[4][4];
        #pragma unroll
        for (int mt = 0; mt < 4; mt++) {
            int r = warpM * 64 + mt * 16 + l15;
            ldsm4(afr[mt], sa + swz(r, lh));
        }
        uint32_t bfr[4][4];
        #pragma unroll
        for (int np = 0; np < 4; np++) {
            int r = warpN * 64 + np * 16 + l15;
            ldsm4(bfr[np], sb + swz(r, lh));
        }
        // 32 MMAs (m16n8k16): b-frag lower 8n = (r0,r2), upper = (r1,r3)
        #pragma unroll
        for (int mt = 0; mt < 4; mt++)
            #pragma unroll
            for (int np = 0; np < 4; np++) {
                mma_f16(c[mt][2 * np], afr[mt], bfr[np][0], bfr[np][2]);
                mma_f16(c[mt][2 * np + 1], afr[mt], bfr[np][1], bfr[np][3]);
            }
    }

    // Epilogue
    #pragma unroll
    for (int mt = 0; mt < 4; mt++)
        #pragma unroll
        for (int nt = 0; nt < 8; nt++) {
            int r = warpM * 64 + mt * 16 + (lane >> 2);
            int cc = warpN * 64 + nt * 8 + (lane & 3) * 2;
            *reinterpret_cast<float2*>(&Cg[(size_t)r * ldc + cc]) =
                make_float2(c[mt][nt][0] * scale, c[mt][nt][1] * scale);
            *reinterpret_cast<float2*>(&Cg[(size_t)(r + 8) * ldc + cc]) =
                make_float2(c[mt][nt][2] * scale, c[mt][nt][3] * scale);
        }
}

// ---------------------------------------------------------------------------
// GEMM kernels
// ---------------------------------------------------------------------------
__global__ __launch_bounds__(NTH)
void mm_qkv(const float* __restrict__ X) {
    const int which = blockIdx.z;
    const int row0 = blockIdx.y * BM, col0 = blockIdx.x * BN;
    const float* A = X + (size_t)row0 * DIM;
    const float* B = g_wt + (size_t)which * DIM * DIM + (size_t)col0 * DIM;
    float* C = ((which == 0) ? g_q : (which == 1) ? g_k : g_v) +
               (size_t)row0 * DIM + col0;
    gemm_core(A, DIM, B, DIM, C, DIM, DIM / BK, 1.0f);
}

__global__ __launch_bounds__(NTH)
void mm_scores(float scale) {
    const int bx = blockIdx.x, by = blockIdx.y;
    if (2 * bx > by) return;  // fully-masked key tile
    const int b = blockIdx.z;
    const int row0 = by * BM, col0 = bx * BN;
    const float* A = g_q + (size_t)b * SEQ * DIM + (size_t)row0 * DIM;
    const float* B = g_k + (size_t)b * SEQ * DIM + (size_t)col0 * DIM;
    float* C = g_sc + (size_t)b * SEQ * SEQ + (size_t)row0 * SEQ + col0;
    gemm_core(A, DIM, B, DIM, C, SEQ, DIM / BK, scale);
}

__global__ __launch_bounds__(NTH)
void mm_pv(float* __restrict__ out) {
    const int b = blockIdx.z;
    const int row0 = blockIdx.y * BM, col0 = blockIdx.x * BN;
    const float* A = g_sc + (size_t)b * SEQ * SEQ + (size_t)row0 * SEQ;
    const float* B = g_vt + (size_t)b * DIM * SEQ + (size_t)col0 * SEQ;
    float* C = out + (size_t)b * SEQ * DIM + (size_t)row0 * DIM + col0;
    gemm_core(A, SEQ, B, SEQ, C, DIM, (row0 + BM) / BK, 1.0f);
}

// ---------------------------------------------------------------------------
// Transposes
// ---------------------------------------------------------------------------
__global__ void tr_w(const float* __restrict__ Wq, const float* __restrict__ Wk,
                     const float* __restrict__ Wv) {
    __shared__ float t[32][33];
    const int z = blockIdx.z;
    const float* S = (z == 0) ? Wq : (z == 1) ? Wk : Wv;
    float* D = g_wt + (size_t)z * DIM * DIM;
    const int x0 = blockIdx.x * 32, y0 = blockIdx.y * 32;
    const int tx = threadIdx.x, ty = threadIdx.y;
    #pragma unroll
    for (int j = 0; j < 32; j += 8)
        t[ty + j][tx] = S[(size_t)(y0 + ty + j) * DIM + x0 + tx];
    __syncthreads();
    #pragma unroll
    for (int j = 0; j < 32; j += 8)
        D[(size_t)(x0 + ty + j) * DIM + y0 + tx] = t[tx][ty + j];
}

__global__ void tr_v() {
    __shared__ float t[32][33];
    const int b = blockIdx.z;
    const float* S = g_v + (size_t)b * SEQ * DIM;
    float* D = g_vt + (size_t)b * DIM * SEQ;
    const int x0 = blockIdx.x * 32, y0 = blockIdx.y * 32;
    const int tx = threadIdx.x, ty = threadIdx.y;
    #pragma unroll
    for (int j = 0; j < 32; j += 8)
        t[ty + j][tx] = S[(size_t)(y0 + ty + j) * DIM + x0 + tx];
    __syncthreads();
    #pragma unroll
    for (int j = 0; j < 32; j += 8)
        D[(size_t)(x0 + ty + j) * SEQ + y0 + tx] = t[tx][ty + j];
}

// ---------------------------------------------------------------------------
// Causal softmax (smem row cache); zero-fill to own 128-block end.
// ---------------------------------------------------------------------------
__global__ __launch_bounds__(NTH)
void softmax_causal() {
    __shared__ float buf[SEQ];
    __shared__ float red[8];
    const int row = blockIdx.x;
    const int q = row & (SEQ - 1);
    float* __restrict__ p = g_sc + (size_t)row * SEQ;
    const int n = q + 1;
    const int limit = (q & ~127) + 128;
    const int tid = threadIdx.x, lane = tid & 31, warp = tid >> 5;

    float m = -1e30f;
    for (int i = tid; i < n; i += NTH) {
        float v = p[i];
        buf[i] = v;
        m = fmaxf(m, v);
    }
    #pragma unroll
    for (int o = 16; o > 0; o >>= 1) m = fmaxf(m, __shfl_xor_sync(~0u, m, o));
    if (lane == 0) red[warp] = m;
    __syncthreads();
    m = red[lane & 7];
    #pragma unroll
    for (int o = 4; o > 0; o >>= 1) m = fmaxf(m, __shfl_xor_sync(~0u, m, o));

    float sum = 0.0f;
    for (int i = tid; i < n; i += NTH) {
        float e = __expf(buf[i] - m);
        buf[i] = e;
        sum += e;
    }
    #pragma unroll
    for (int o = 16; o > 0; o >>= 1) sum += __shfl_xor_sync(~0u, sum, o);
    __syncthreads();
    if (lane == 0) red[warp] = sum;
    __syncthreads();
    sum = red[lane & 7];
    #pragma unroll
    for (int o = 4; o > 0; o >>= 1) sum += __shfl_xor_sync(~0u, sum, o);
    const float inv = 1.0f / sum;

    for (int i = tid; i < n; i += NTH) p[i] = buf[i] * inv;
    for (int i = n + tid; i < limit; i += NTH) p[i] = 0.0f;
}

// ---------------------------------------------------------------------------
extern "C" void kernel_launch(void* const* d_in, const int* in_sizes, int n_in,
                              void* d_out, int out_size) {
    const float* x  = (const float*)d_in[0];
    const float* Wq = (const float*)d_in[1];
    const float* Wk = (const float*)d_in[2];
    const float* Wv = (const float*)d_in[3];
    float* out = (float*)d_out;

    // 1) W^T
    tr_w<<<dim3(32, 32, 3), dim3(32, 8)>>>(Wq, Wk, Wv);
    // 2) QKV projections
    mm_qkv<<<dim3(DIM / BN, MROWS / BM, 3), NTH>>>(x);
    // 3) V^T
    tr_v<<<dim3(DIM / 32, SEQ / 32, BATCH), dim3(32, 8)>>>();
    // 4) scores (lower-triangular tiles)
    const float scale = 1.0f / sqrtf((float)DIM);
    mm_scores<<<dim3(SEQ / BN, SEQ / BM, BATCH), NTH>>>(scale);
    // 5) softmax
    softmax_causal<<<BATCH * SEQ, NTH>>>();
    // 6) out = P V
    mm_pv<<<dim3(DIM / BN, SEQ / BM, BATCH), NTH>>>(out);
}

// round 8
// speedup vs baseline: 2.5325x; 1.2474x over previous
#include <cuda_runtime.h>
#include <cuda_fp16.h>
#include <math.h>
#include <stdint.h>

#define BATCH 4
#define SEQ   2048
#define DIM   1024
#define MROWS (BATCH * SEQ)

// Scratch (__device__ globals). All GEMM inputs live in gmem as fp16
// (rounded once at the producer), so GEMM loads are raw and conversion-free.
__device__ __half g_xh[MROWS * DIM];
__device__ __half g_qh[BATCH * SEQ * DIM];
__device__ __half g_kh[BATCH * SEQ * DIM];
__device__ __half g_vh[BATCH * SEQ * DIM];
__device__ __half g_vth[BATCH * DIM * SEQ];          // V^T [dim][seq]
__device__ __half g_wth[3 * DIM * DIM];              // W^T [n][k]
__device__ float  g_sc[(size_t)BATCH * SEQ * SEQ];   // raw scores (fp32)
__device__ __half g_ph[(size_t)BATCH * SEQ * SEQ];   // probs (fp16)

// GEMM config: CTA 128x256xBK32 (halves); 8 warps 2(M)x4(N); warp tile 64x64.
#define BM 128
#define BN 256
#define BK 32
#define NTH 256

// smem: fp16 rows of BK=32 halves = 64 B = 4 x 16B chunks; double buffered.
// byte addr(row, chunk) = row*64 + (chunk ^ ((row>>1)&3))*16.
// 16B-group(row,c) = (4*row + c^((row>>1)&3)) mod 8: distinct over any 8
// consecutive rows at fixed c (ldmatrix phases) and 4-wavefront-minimal for
// the 8-row x 4-chunk STS phases.
__device__ __forceinline__ uint32_t swz(int row, int chunk) {
    return (uint32_t)(row << 6) + ((uint32_t)(chunk ^ ((row >> 1) & 3)) << 4);
}

#define A_BUF 8192     // 128 * 64
#define B_BUF 16384    // 256 * 64
#define SM_B  (2 * A_BUF)

// ---------------------------------------------------------------------------
// helpers
// ---------------------------------------------------------------------------
__device__ __forceinline__ uint32_t smem_u32(const void* p) {
    uint32_t a;
    asm("{ .reg .u64 t; cvta.to.shared.u64 t, %1; cvt.u32.u64 %0, t; }"
        : "=r"(a) : "l"(p));
    return a;
}

__device__ __forceinline__ void ldsm4(uint32_t r[4], uint32_t addr) {
    asm volatile("ldmatrix.sync.aligned.m8n8.x4.shared.b16 {%0,%1,%2,%3}, [%4];"
                 : "=r"(r[0]), "=r"(r[1]), "=r"(r[2]), "=r"(r[3]) : "r"(addr));
}

__device__ __forceinline__ void mma_f16(float c[4], const uint32_t a[4],
                                        uint32_t b0, uint32_t b1) {
    asm volatile(
        "mma.sync.aligned.m16n8k16.row.col.f32.f16.f16.f32 "
        "{%0,%1,%2,%3}, {%4,%5,%6,%7}, {%8,%9}, {%0,%1,%2,%3};"
        : "+f"(c[0]), "+f"(c[1]), "+f"(c[2]), "+f"(c[3])
        : "r"(a[0]), "r"(a[1]), "r"(a[2]), "r"(a[3]), "r"(b0), "r"(b1));
}

// ---------------------------------------------------------------------------
// Core: C[128x256] = A[128 x nk*32] @ B^T; A, B fp16 K-major rows in gmem.
// Register prefetch, double-buffered smem, one barrier per BK=32 iteration.
// HALF_OUT: write C as fp16 (producer rounding); else fp32.
// ---------------------------------------------------------------------------
template <bool HALF_OUT>
__device__ __forceinline__ void gemm_core(const __half* __restrict__ Ag, int lda,
                                          const __half* __restrict__ Bg, int ldb,
                                          void* __restrict__ Cg, int ldc,
                                          int nk, float scale) {
    __shared__ uint4 smbuf[(2 * (A_BUF + B_BUF)) / 16];   // 48 KB
    const uint32_t sm = smem_u32(smbuf);
    char* const smc = reinterpret_cast<char*>(smbuf);

    const int tid = threadIdx.x, lane = tid & 31, warp = tid >> 5;
    const int warpM = warp >> 2, warpN = warp & 3;
    const int l15 = lane & 15, lh = lane >> 4;

    float c[4][8][4] = {};
    uint4 pa[2], pb[4];

    // LDG stage 0: idx -> row = idx>>2, chunk = idx&3 (16 B of halves)
    #pragma unroll
    for (int t = 0; t < 2; t++) {
        int idx = tid + t * NTH;
        pa[t] = *reinterpret_cast<const uint4*>(
            Ag + (size_t)(idx >> 2) * lda + ((idx & 3) << 3));
    }
    #pragma unroll
    for (int t = 0; t < 4; t++) {
        int idx = tid + t * NTH;
        pb[t] = *reinterpret_cast<const uint4*>(
            Bg + (size_t)(idx >> 2) * ldb + ((idx & 3) << 3));
    }
    // STS stage 0 -> buffer 0
    #pragma unroll
    for (int t = 0; t < 2; t++) {
        int idx = tid + t * NTH;
        *reinterpret_cast<uint4*>(smc + swz(idx >> 2, idx & 3)) = pa[t];
    }
    #pragma unroll
    for (int t = 0; t < 4; t++) {
        int idx = tid + t * NTH;
        *reinterpret_cast<uint4*>(smc + SM_B + swz(idx >> 2, idx & 3)) = pb[t];
    }
    __syncthreads();

    for (int i = 0; i < nk; i++) {
        const uint32_t abase = sm + (i & 1) * A_BUF;
        const uint32_t bbase = sm + SM_B + (i & 1) * B_BUF;
        // LDG stage i+1 (latency hidden behind compute)
        if (i + 1 < nk) {
            const int kb = (i + 1) * BK;
            #pragma unroll
            for (int t = 0; t < 2; t++) {
                int idx = tid + t * NTH;
                pa[t] = *reinterpret_cast<const uint4*>(
                    Ag + (size_t)(idx >> 2) * lda + kb + ((idx & 3) << 3));
            }
            #pragma unroll
            for (int t = 0; t < 4; t++) {
                int idx = tid + t * NTH;
                pb[t] = *reinterpret_cast<const uint4*>(
                    Bg + (size_t)(idx >> 2) * ldb + kb + ((idx & 3) << 3));
            }
        }
        // compute 2 k16 steps from buffer i&1
        #pragma unroll
        for (int s = 0; s < 2; s++) {
            uint32_t afr[4][4];
            #pragma unroll
            for (int mt = 0; mt < 4; mt++)
                ldsm4(afr[mt], abase + swz(warpM * 64 + mt * 16 + l15, 2 * s + lh));
            uint32_t bfr[4][4];
            #pragma unroll
            for (int np = 0; np < 4; np++)
                ldsm4(bfr[np], bbase + swz(warpN * 64 + np * 16 + l15, 2 * s + lh));
            #pragma unroll
            for (int mt = 0; mt < 4; mt++)
                #pragma unroll
                for (int np = 0; np < 4; np++) {
                    mma_f16(c[mt][2 * np], afr[mt], bfr[np][0], bfr[np][2]);
                    mma_f16(c[mt][2 * np + 1], afr[mt], bfr[np][1], bfr[np][3]);
                }
        }
        // STS stage i+1 -> other buffer
        if (i + 1 < nk) {
            char* const ab = smc + ((i + 1) & 1) * A_BUF;
            char* const bb = smc + SM_B + ((i + 1) & 1) * B_BUF;
            #pragma unroll
            for (int t = 0; t < 2; t++) {
                int idx = tid + t * NTH;
                *reinterpret_cast<uint4*>(ab + swz(idx >> 2, idx & 3)) = pa[t];
            }
            #pragma unroll
            for (int t = 0; t < 4; t++) {
                int idx = tid + t * NTH;
                *reinterpret_cast<uint4*>(bb + swz(idx >> 2, idx & 3)) = pb[t];
            }
        }
        __syncthreads();
    }

    // Epilogue
    #pragma unroll
    for (int mt = 0; mt < 4; mt++)
        #pragma unroll
        for (int nt = 0; nt < 8; nt++) {
            int r = warpM * 64 + mt * 16 + (lane >> 2);
            int cc = warpN * 64 + nt * 8 + (lane & 3) * 2;
            float v0 = c[mt][nt][0] * scale, v1 = c[mt][nt][1] * scale;
            float v2 = c[mt][nt][2] * scale, v3 = c[mt][nt][3] * scale;
            if (HALF_OUT) {
                __half* C = reinterpret_cast<__half*>(Cg);
                *reinterpret_cast<__half2*>(&C[(size_t)r * ldc + cc]) =
                    __floats2half2_rn(v0, v1);
                *reinterpret_cast<__half2*>(&C[(size_t)(r + 8) * ldc + cc]) =
                    __floats2half2_rn(v2, v3);
            } else {
                float* C = reinterpret_cast<float*>(Cg);
                *reinterpret_cast<float2*>(&C[(size_t)r * ldc + cc]) =
                    make_float2(v0, v1);
                *reinterpret_cast<float2*>(&C[(size_t)(r + 8) * ldc + cc]) =
                    make_float2(v2, v3);
            }
        }
}

// ---------------------------------------------------------------------------
// GEMM kernels
// ---------------------------------------------------------------------------
__global__ __launch_bounds__(NTH)
void mm_qkv() {
    const int which = blockIdx.z;
    const int row0 = blockIdx.y * BM, col0 = blockIdx.x * BN;
    const __half* A = g_xh + (size_t)row0 * DIM;
    const __half* B = g_wth + (size_t)which * DIM * DIM + (size_t)col0 * DIM;
    __half* C = ((which == 0) ? g_qh : (which == 1) ? g_kh : g_vh) +
                (size_t)row0 * DIM + col0;
    gemm_core<true>(A, DIM, B, DIM, C, DIM, DIM / BK, 1.0f);
}

__global__ __launch_bounds__(NTH)
void mm_scores(float scale) {
    const int bx = blockIdx.x, by = blockIdx.y;
    if (2 * bx > by) return;  // fully-masked key tile
    const int b = blockIdx.z;
    const int row0 = by * BM, col0 = bx * BN;
    const __half* A = g_qh + (size_t)b * SEQ * DIM + (size_t)row0 * DIM;
    const __half* B = g_kh + (size_t)b * SEQ * DIM + (size_t)col0 * DIM;
    float* C = g_sc + (size_t)b * SEQ * SEQ + (size_t)row0 * SEQ + col0;
    gemm_core<false>(A, DIM, B, DIM, C, SEQ, DIM / BK, scale);
}

__global__ __launch_bounds__(NTH)
void mm_pv(float* __restrict__ out) {
    const int b = blockIdx.z;
    const int row0 = blockIdx.y * BM, col0 = blockIdx.x * BN;
    const __half* A = g_ph + (size_t)b * SEQ * SEQ + (size_t)row0 * SEQ;
    const __half* B = g_vth + (size_t)b * DIM * SEQ + (size_t)col0 * SEQ;
    float* C = out + (size_t)b * SEQ * DIM + (size_t)row0 * DIM + col0;
    gemm_core<false>(A, SEQ, B, SEQ, C, DIM, 4 * (blockIdx.y + 1), 1.0f);
}

// ---------------------------------------------------------------------------
// Prep: x -> fp16; W -> fp16 W^T; V(half) -> V^T(half)
// ---------------------------------------------------------------------------
__global__ void round_x(const float* __restrict__ x) {
    size_t i = (size_t)(blockIdx.x * blockDim.x + threadIdx.x) * 4;
    float4 v = *reinterpret_cast<const float4*>(x + i);
    __half2 h01 = __floats2half2_rn(v.x, v.y);
    __half2 h23 = __floats2half2_rn(v.z, v.w);
    *reinterpret_cast<__half2*>(g_xh + i) = h01;
    *reinterpret_cast<__half2*>(g_xh + i + 2) = h23;
}

__global__ void tr_w(const float* __restrict__ Wq, const float* __restrict__ Wk,
                     const float* __restrict__ Wv) {
    __shared__ float t[32][33];
    const int z = blockIdx.z;
    const float* S = (z == 0) ? Wq : (z == 1) ? Wk : Wv;
    __half* D = g_wth + (size_t)z * DIM * DIM;
    const int x0 = blockIdx.x * 32, y0 = blockIdx.y * 32;
    const int tx = threadIdx.x, ty = threadIdx.y;
    #pragma unroll
    for (int j = 0; j < 32; j += 8)
        t[ty + j][tx] = S[(size_t)(y0 + ty + j) * DIM + x0 + tx];
    __syncthreads();
    #pragma unroll
    for (int j = 0; j < 32; j += 8)
        D[(size_t)(x0 + ty + j) * DIM + y0 + tx] = __float2half_rn(t[tx][ty + j]);
}

__global__ void tr_v() {
    __shared__ __half t[32][40];
    const int b = blockIdx.z;
    const __half* S = g_vh + (size_t)b * SEQ * DIM;
    __half* D = g_vth + (size_t)b * DIM * SEQ;
    const int x0 = blockIdx.x * 32, y0 = blockIdx.y * 32;
    const int tx = threadIdx.x, ty = threadIdx.y;
    #pragma unroll
    for (int j = 0; j < 32; j += 8)
        t[ty + j][tx] = S[(size_t)(y0 + ty + j) * DIM + x0 + tx];
    __syncthreads();
    #pragma unroll
    for (int j = 0; j < 32; j += 8)
        D[(size_t)(x0 + ty + j) * SEQ + y0 + tx] = t[tx][ty + j];
}

// ---------------------------------------------------------------------------
// Causal softmax: fp32 scores in, fp16 probs out; zero-fill to block end.
// ---------------------------------------------------------------------------
__global__ __launch_bounds__(NTH)
void softmax_causal() {
    __shared__ float buf[SEQ];
    __shared__ float red[8];
    const int row = blockIdx.x;
    const int q = row & (SEQ - 1);
    const float* __restrict__ p = g_sc + (size_t)row * SEQ;
    __half* __restrict__ ph = g_ph + (size_t)row * SEQ;
    const int n = q + 1;
    const int limit = (q & ~127) + 128;
    const int tid = threadIdx.x, lane = tid & 31, warp = tid >> 5;

    float m = -1e30f;
    for (int i = tid; i < n; i += NTH) {
        float v = p[i];
        buf[i] = v;
        m = fmaxf(m, v);
    }
    #pragma unroll
    for (int o = 16; o > 0; o >>= 1) m = fmaxf(m, __shfl_xor_sync(~0u, m, o));
    if (lane == 0) red[warp] = m;
    __syncthreads();
    m = red[lane & 7];
    #pragma unroll
    for (int o = 4; o > 0; o >>= 1) m = fmaxf(m, __shfl_xor_sync(~0u, m, o));

    float sum = 0.0f;
    for (int i = tid; i < n; i += NTH) {
        float e = __expf(buf[i] - m);
        buf[i] = e;
        sum += e;
    }
    #pragma unroll
    for (int o = 16; o > 0; o >>= 1) sum += __shfl_xor_sync(~0u, sum, o);
    __syncthreads();
    if (lane == 0) red[warp] = sum;
    __syncthreads();
    sum = red[lane & 7];
    #pragma unroll
    for (int o = 4; o > 0; o >>= 1) sum += __shfl_xor_sync(~0u, sum, o);
    const float inv = 1.0f / sum;

    for (int i = tid; i < n; i += NTH) ph[i] = __float2half_rn(buf[i] * inv);
    for (int i = n + tid; i < limit; i += NTH) ph[i] = __float2half_rn(0.0f);
}

// ---------------------------------------------------------------------------
extern "C" void kernel_launch(void* const* d_in, const int* in_sizes, int n_in,
                              void* d_out, int out_size) {
    const float* x  = (const float*)d_in[0];
    const float* Wq = (const float*)d_in[1];
    const float* Wk = (const float*)d_in[2];
    const float* Wv = (const float*)d_in[3];
    float* out = (float*)d_out;

    // 1) x -> fp16, W^T -> fp16
    round_x<<<(MROWS * DIM) / (4 * NTH), NTH>>>(x);
    tr_w<<<dim3(32, 32, 3), dim3(32, 8)>>>(Wq, Wk, Wv);
    // 2) QKV projections (fp16 out)
    mm_qkv<<<dim3(DIM / BN, MROWS / BM, 3), NTH>>>();
    // 3) V^T
    tr_v<<<dim3(DIM / 32, SEQ / 32, BATCH), dim3(32, 8)>>>();
    // 4) scores (lower-triangular tiles)
    const float scale = 1.0f / sqrtf((float)DIM);
    mm_scores<<<dim3(SEQ / BN, SEQ / BM, BATCH), NTH>>>(scale);
    // 5) softmax (fp16 probs)
    softmax_causal<<<BATCH * SEQ, NTH>>>();
    // 6) out = P V
    mm_pv<<<dim3(DIM / BN, SEQ / BM, BATCH), NTH>>>(out);
}

// round 9
// speedup vs baseline: 2.6047x; 1.0285x over previous
#include <cuda_runtime.h>
#include <cuda_fp16.h>
#include <math.h>
#include <stdint.h>

#define BATCH 4
#define SEQ   2048
#define DIM   1024
#define MROWS (BATCH * SEQ)

// Scratch (__device__ globals). GEMM inputs in fp16 (rounded at producer).
__device__ __half g_xh[MROWS * DIM];
__device__ __half g_qh[BATCH * SEQ * DIM];
__device__ __half g_kh[BATCH * SEQ * DIM];
__device__ __half g_vh[BATCH * SEQ * DIM];
__device__ __half g_vth[BATCH * DIM * SEQ];          // V^T [dim][seq]
__device__ __half g_wth[3 * DIM * DIM];              // W^T [n][k]
__device__ __half g_ph[(size_t)BATCH * SEQ * SEQ];   // unnormalized exp(score)
__device__ float  g_psum[(size_t)MROWS * 32];        // partial row sums
__device__ float  g_rinv[MROWS];                     // 1 / row sum

// GEMM config: CTA 128x256xBK32 (halves); 8 warps 2(M)x4(N); warp tile 64x64.
#define BM 128
#define BN 256
#define BK 32
#define NTH 256

// smem: fp16 rows of 32 halves = 64 B = 4 x 16B chunks; double buffered.
// byte addr(row, chunk) = row*64 + (chunk ^ ((row>>1)&3))*16. Conflict-free
// for ldmatrix 8-row phases and 4-wavefront-minimal for STS phases.
__device__ __forceinline__ uint32_t swz(int row, int chunk) {
    return (uint32_t)(row << 6) + ((uint32_t)(chunk ^ ((row >> 1) & 3)) << 4);
}

#define A_BUF 8192     // 128 * 64
#define B_BUF 16384    // 256 * 64
#define SM_B  (2 * A_BUF)

// Epilogue modes
#define MODE_HALF 0    // write fp16 C (QKV projections)
#define MODE_EXP  1    // exp(v*scale), causal mask, fp16 C + psum partials
#define MODE_PV   2    // fp32 C scaled by per-row rinv

// ---------------------------------------------------------------------------
__device__ __forceinline__ uint32_t smem_u32(const void* p) {
    uint32_t a;
    asm("{ .reg .u64 t; cvta.to.shared.u64 t, %1; cvt.u32.u64 %0, t; }"
        : "=r"(a) : "l"(p));
    return a;
}

__device__ __forceinline__ void ldsm4(uint32_t r[4], uint32_t addr) {
    asm volatile("ldmatrix.sync.aligned.m8n8.x4.shared.b16 {%0,%1,%2,%3}, [%4];"
                 : "=r"(r[0]), "=r"(r[1]), "=r"(r[2]), "=r"(r[3]) : "r"(addr));
}

__device__ __forceinline__ void mma_f16(float c[4], const uint32_t a[4],
                                        uint32_t b0, uint32_t b1) {
    asm volatile(
        "mma.sync.aligned.m16n8k16.row.col.f32.f16.f16.f32 "
        "{%0,%1,%2,%3}, {%4,%5,%6,%7}, {%8,%9}, {%0,%1,%2,%3};"
        : "+f"(c[0]), "+f"(c[1]), "+f"(c[2]), "+f"(c[3])
        : "r"(a[0]), "r"(a[1]), "r"(a[2]), "r"(a[3]), "r"(b0), "r"(b1));
}

// ---------------------------------------------------------------------------
// Core: C[128x256] = A[128 x nk*32] @ B^T; fp16 K-major operands in gmem.
// Register prefetch, double-buffered smem, one barrier per iteration.
//   MODE_EXP:  gr0/gc0 = in-batch row/col bases for causal mask;
//              psum = &g_psum[(bRowBase)*32 + bx*4] (stride 32 per row)
//   MODE_PV:   rinv = &g_rinv[bRowBase]
// ---------------------------------------------------------------------------
template <int MODE>
__device__ __forceinline__ void gemm_core(const __half* __restrict__ Ag, int lda,
                                          const __half* __restrict__ Bg, int ldb,
                                          void* __restrict__ Cg, int ldc,
                                          int nk, float scale,
                                          int gr0, int gc0,
                                          float* __restrict__ psum,
                                          const float* __restrict__ rinv) {
    __shared__ uint4 smbuf[(2 * (A_BUF + B_BUF)) / 16];   // 48 KB
    const uint32_t sm = smem_u32(smbuf);
    char* const smc = reinterpret_cast<char*>(smbuf);

    const int tid = threadIdx.x, lane = tid & 31, warp = tid >> 5;
    const int warpM = warp >> 2, warpN = warp & 3;
    const int l15 = lane & 15, lh = lane >> 4;

    float c[4][8][4] = {};
    uint4 pa[2], pb[4];

    #pragma unroll
    for (int t = 0; t < 2; t++) {
        int idx = tid + t * NTH;
        pa[t] = *reinterpret_cast<const uint4*>(
            Ag + (size_t)(idx >> 2) * lda + ((idx & 3) << 3));
    }
    #pragma unroll
    for (int t = 0; t < 4; t++) {
        int idx = tid + t * NTH;
        pb[t] = *reinterpret_cast<const uint4*>(
            Bg + (size_t)(idx >> 2) * ldb + ((idx & 3) << 3));
    }
    #pragma unroll
    for (int t = 0; t < 2; t++) {
        int idx = tid + t * NTH;
        *reinterpret_cast<uint4*>(smc + swz(idx >> 2, idx & 3)) = pa[t];
    }
    #pragma unroll
    for (int t = 0; t < 4; t++) {
        int idx = tid + t * NTH;
        *reinterpret_cast<uint4*>(smc + SM_B + swz(idx >> 2, idx & 3)) = pb[t];
    }
    __syncthreads();

    for (int i = 0; i < nk; i++) {
        const uint32_t abase = sm + (i & 1) * A_BUF;
        const uint32_t bbase = sm + SM_B + (i & 1) * B_BUF;
        if (i + 1 < nk) {
            const int kb = (i + 1) * BK;
            #pragma unroll
            for (int t = 0; t < 2; t++) {
                int idx = tid + t * NTH;
                pa[t] = *reinterpret_cast<const uint4*>(
                    Ag + (size_t)(idx >> 2) * lda + kb + ((idx & 3) << 3));
            }
            #pragma unroll
            for (int t = 0; t < 4; t++) {
                int idx = tid + t * NTH;
                pb[t] = *reinterpret_cast<const uint4*>(
                    Bg + (size_t)(idx >> 2) * ldb + kb + ((idx & 3) << 3));
            }
        }
        #pragma unroll
        for (int s = 0; s < 2; s++) {
            uint32_t afr[4][4];
            #pragma unroll
            for (int mt = 0; mt < 4; mt++)
                ldsm4(afr[mt], abase + swz(warpM * 64 + mt * 16 + l15, 2 * s + lh));
            uint32_t bfr[4][4];
            #pragma unroll
            for (int np = 0; np < 4; np++)
                ldsm4(bfr[np], bbase + swz(warpN * 64 + np * 16 + l15, 2 * s + lh));
            #pragma unroll
            for (int mt = 0; mt < 4; mt++)
                #pragma unroll
                for (int np = 0; np < 4; np++) {
                    mma_f16(c[mt][2 * np], afr[mt], bfr[np][0], bfr[np][2]);
                    mma_f16(c[mt][2 * np + 1], afr[mt], bfr[np][1], bfr[np][3]);
                }
        }
        if (i + 1 < nk) {
            char* const ab = smc + ((i + 1) & 1) * A_BUF;
            char* const bb = smc + SM_B + ((i + 1) & 1) * B_BUF;
            #pragma unroll
            for (int t = 0; t < 2; t++) {
                int idx = tid + t * NTH;
                *reinterpret_cast<uint4*>(ab + swz(idx >> 2, idx & 3)) = pa[t];
            }
            #pragma unroll
            for (int t = 0; t < 4; t++) {
                int idx = tid + t * NTH;
                *reinterpret_cast<uint4*>(bb + swz(idx >> 2, idx & 3)) = pb[t];
            }
        }
        __syncthreads();
    }

    // Epilogue
    #pragma unroll
    for (int mt = 0; mt < 4; mt++) {
        const int rl0 = warpM * 64 + mt * 16 + (lane >> 2);   // local row
        float rs0 = 0.0f, rs1 = 0.0f;                          // MODE_EXP sums
        float inv0 = 1.0f, inv1 = 1.0f;
        if (MODE == MODE_PV) {
            inv0 = rinv[rl0];
            inv1 = rinv[rl0 + 8];
        }
        #pragma unroll
        for (int nt = 0; nt < 8; nt++) {
            const int cl = warpN * 64 + nt * 8 + (lane & 3) * 2;  // local col
            float v0 = c[mt][nt][0], v1 = c[mt][nt][1];
            float v2 = c[mt][nt][2], v3 = c[mt][nt][3];
            if (MODE == MODE_HALF) {
                __half* C = reinterpret_cast<__half*>(Cg);
                *reinterpret_cast<__half2*>(&C[(size_t)rl0 * ldc + cl]) =
                    __floats2half2_rn(v0, v1);
                *reinterpret_cast<__half2*>(&C[(size_t)(rl0 + 8) * ldc + cl]) =
                    __floats2half2_rn(v2, v3);
            } else if (MODE == MODE_EXP) {
                const int gc = gc0 + cl;
                const int r0 = gr0 + rl0, r1 = r0 + 8;
                float e0 = (gc     <= r0) ? __expf(v0 * scale) : 0.0f;
                float e1 = (gc + 1 <= r0) ? __expf(v1 * scale) : 0.0f;
                float e2 = (gc     <= r1) ? __expf(v2 * scale) : 0.0f;
                float e3 = (gc + 1 <= r1) ? __expf(v3 * scale) : 0.0f;
                rs0 += e0 + e1;
                rs1 += e2 + e3;
                __half* C = reinterpret_cast<__half*>(Cg);
                *reinterpret_cast<__half2*>(&C[(size_t)rl0 * ldc + cl]) =
                    __floats2half2_rn(e0, e1);
                *reinterpret_cast<__half2*>(&C[(size_t)(rl0 + 8) * ldc + cl]) =
                    __floats2half2_rn(e2, e3);
            } else {  // MODE_PV
                float* C = reinterpret_cast<float*>(Cg);
                *reinterpret_cast<float2*>(&C[(size_t)rl0 * ldc + cl]) =
                    make_float2(v0 * inv0, v1 * inv0);
                *reinterpret_cast<float2*>(&C[(size_t)(rl0 + 8) * ldc + cl]) =
                    make_float2(v2 * inv1, v3 * inv1);
            }
        }
        if (MODE == MODE_EXP) {
            // reduce across the 4 lanes sharing each row
            #pragma unroll
            for (int o = 1; o < 4; o <<= 1) {
                rs0 += __shfl_xor_sync(~0u, rs0, o);
                rs1 += __shfl_xor_sync(~0u, rs1, o);
            }
            if ((lane & 3) == 0) {
                psum[(size_t)rl0 * 32 + warpN] = rs0;
                psum[(size_t)(rl0 + 8) * 32 + warpN] = rs1;
            }
        }
    }
}

// ---------------------------------------------------------------------------
// GEMM kernels
// ---------------------------------------------------------------------------
__global__ __launch_bounds__(NTH)
void mm_qkv() {
    const int which = blockIdx.z;
    const int row0 = blockIdx.y * BM, col0 = blockIdx.x * BN;
    const __half* A = g_xh + (size_t)row0 * DIM;
    const __half* B = g_wth + (size_t)which * DIM * DIM + (size_t)col0 * DIM;
    __half* C = ((which == 0) ? g_qh : (which == 1) ? g_kh : g_vh) +
                (size_t)row0 * DIM + col0;
    gemm_core<MODE_HALF>(A, DIM, B, DIM, C, DIM, DIM / BK, 1.0f,
                         0, 0, nullptr, nullptr);
}

__global__ __launch_bounds__(NTH)
void mm_scores(float scale) {
    const int bx = blockIdx.x, by = blockIdx.y;
    if (2 * bx > by) return;  // fully-masked key tile
    const int b = blockIdx.z;
    const int row0 = by * BM, col0 = bx * BN;
    const __half* A = g_qh + (size_t)b * SEQ * DIM + (size_t)row0 * DIM;
    const __half* B = g_kh + (size_t)b * SEQ * DIM + (size_t)col0 * DIM;
    __half* C = g_ph + (size_t)b * SEQ * SEQ + (size_t)row0 * SEQ + col0;
    float* psum = g_psum + (size_t)(b * SEQ + row0) * 32 + bx * 4;
    gemm_core<MODE_EXP>(A, DIM, B, DIM, C, SEQ, DIM / BK, scale,
                        row0, col0, psum, nullptr);
}

__global__ __launch_bounds__(NTH)
void mm_pv(float* __restrict__ out) {
    const int b = blockIdx.z;
    const int row0 = blockIdx.y * BM, col0 = blockIdx.x * BN;
    const __half* A = g_ph + (size_t)b * SEQ * SEQ + (size_t)row0 * SEQ;
    const __half* B = g_vth + (size_t)b * DIM * SEQ + (size_t)col0 * SEQ;
    float* C = out + (size_t)b * SEQ * DIM + (size_t)row0 * DIM + col0;
    const float* rinv = g_rinv + (size_t)b * SEQ + row0;
    gemm_core<MODE_PV>(A, SEQ, B, SEQ, C, DIM, 4 * (blockIdx.y + 1), 1.0f,
                       0, 0, nullptr, rinv);
}

// ---------------------------------------------------------------------------
// Row-sum finalize: deterministic (no atomics). One thread per row.
// ---------------------------------------------------------------------------
__global__ __launch_bounds__(NTH)
void reduce_rinv() {
    const int row = blockIdx.x * NTH + threadIdx.x;   // b*SEQ + q
    const int q = row & (SEQ - 1);
    const int nw = ((q >> 8) + 1) * 4;                // valid psum slots
    const float* p = g_psum + (size_t)row * 32;
    float s = 0.0f;
    for (int j = 0; j < nw; j++) s += p[j];
    g_rinv[row] = 1.0f / s;
}

// ---------------------------------------------------------------------------
// Prep: x -> fp16; W -> fp16 W^T; V(half) -> V^T(half)
// ---------------------------------------------------------------------------
__global__ void round_x(const float* __restrict__ x) {
    size_t i = (size_t)(blockIdx.x * blockDim.x + threadIdx.x) * 4;
    float4 v = *reinterpret_cast<const float4*>(x + i);
    *reinterpret_cast<__half2*>(g_xh + i) = __floats2half2_rn(v.x, v.y);
    *reinterpret_cast<__half2*>(g_xh + i + 2) = __floats2half2_rn(v.z, v.w);
}

__global__ void tr_w(const float* __restrict__ Wq, const float* __restrict__ Wk,
                     const float* __restrict__ Wv) {
    __shared__ float t[32][33];
    const int z = blockIdx.z;
    const float* S = (z == 0) ? Wq : (z == 1) ? Wk : Wv;
    __half* D = g_wth + (size_t)z * DIM * DIM;
    const int x0 = blockIdx.x * 32, y0 = blockIdx.y * 32;
    const int tx = threadIdx.x, ty = threadIdx.y;
    #pragma unroll
    for (int j = 0; j < 32; j += 8)
        t[ty + j][tx] = S[(size_t)(y0 + ty + j) * DIM + x0 + tx];
    __syncthreads();
    #pragma unroll
    for (int j = 0; j < 32; j += 8)
        D[(size_t)(x0 + ty + j) * DIM + y0 + tx] = __float2half_rn(t[tx][ty + j]);
}

__global__ void tr_v() {
    __shared__ __half t[32][40];
    const int b = blockIdx.z;
    const __half* S = g_vh + (size_t)b * SEQ * DIM;
    __half* D = g_vth + (size_t)b * DIM * SEQ;
    const int x0 = blockIdx.x * 32, y0 = blockIdx.y * 32;
    const int tx = threadIdx.x, ty = threadIdx.y;
    #pragma unroll
    for (int j = 0; j < 32; j += 8)
        t[ty + j][tx] = S[(size_t)(y0 + ty + j) * DIM + x0 + tx];
    __syncthreads();
    #pragma unroll
    for (int j = 0; j < 32; j += 8)
        D[(size_t)(x0 + ty + j) * SEQ + y0 + tx] = t[tx][ty + j];
}

// ---------------------------------------------------------------------------
extern "C" void kernel_launch(void* const* d_in, const int* in_sizes, int n_in,
                              void* d_out, int out_size) {
    const float* x  = (const float*)d_in[0];
    const float* Wq = (const float*)d_in[1];
    const float* Wk = (const float*)d_in[2];
    const float* Wv = (const float*)d_in[3];
    float* out = (float*)d_out;

    // 1) x -> fp16, W^T -> fp16
    round_x<<<(MROWS * DIM) / (4 * NTH), NTH>>>(x);
    tr_w<<<dim3(32, 32, 3), dim3(32, 8)>>>(Wq, Wk, Wv);
    // 2) QKV projections (fp16 out)
    mm_qkv<<<dim3(DIM / BN, MROWS / BM, 3), NTH>>>();
    // 3) V^T
    tr_v<<<dim3(DIM / 32, SEQ / 32, BATCH), dim3(32, 8)>>>();
    // 4) exp(scores) + partial row sums (lower-triangular tiles)
    const float scale = 1.0f / sqrtf((float)DIM);
    mm_scores<<<dim3(SEQ / BN, SEQ / BM, BATCH), NTH>>>(scale);
    // 5) finalize 1/rowsum
    reduce_rinv<<<MROWS / NTH, NTH>>>();
    // 6) out = (P V) * rinv
    mm_pv<<<dim3(DIM / BN, SEQ / BM, BATCH), NTH>>>(out);
}

// round 10
// speedup vs baseline: 3.1134x; 1.1953x over previous
#include <cuda_runtime.h>
#include <cuda_fp16.h>
#include <math.h>
#include <stdint.h>

#define BATCH 4
#define SEQ   2048
#define DIM   1024
#define MROWS (BATCH * SEQ)

// Scratch (__device__ globals). GEMM inputs in fp16 (rounded at producer).
__device__ __half g_xh[MROWS * DIM];
__device__ __half g_qh[BATCH * SEQ * DIM];
__device__ __half g_kh[BATCH * SEQ * DIM];
__device__ __half g_vh[BATCH * SEQ * DIM];
__device__ __half g_vth[BATCH * DIM * SEQ];          // V^T [dim][seq]
__device__ __half g_wth[3 * DIM * DIM];              // W^T [n][k]
__device__ __half g_ph[(size_t)BATCH * SEQ * SEQ];   // unnormalized exp(score)
__device__ float  g_psum[(size_t)MROWS * 32];        // partial row sums
__device__ float  g_rinv[MROWS];                     // 1 / row sum

// GEMM config: CTA 128x256xBK64 (halves); 8 warps 2(M)x4(N); warp tile 64x64.
// 3-stage cp.async pipeline, 48 KB per stage (A 16K + B 32K), 144 KB total.
#define BM 128
#define BN 256
#define BK 64
#define NTH 256
#define STAGES 3
#define A_BUF 16384                  // 128 rows * 128 B
#define B_BUF 32768                  // 256 rows * 128 B
#define STAGE_BYTES (A_BUF + B_BUF)  // 49152
#define SMEM_TOTAL (STAGES * STAGE_BYTES)  // 147456

// Row = 64 halves = 128 B = 8 x 16B chunks. addr = row*128 + (c ^ (row&7))*16.
// ldmatrix phase (8 consecutive rows, fixed c): groups c^(row&7) all distinct.
__device__ __forceinline__ uint32_t swz(int row, int chunk) {
    return ((uint32_t)row << 7) + ((uint32_t)(chunk ^ (row & 7)) << 4);
}

// Epilogue modes
#define MODE_HALF 0
#define MODE_EXP  1
#define MODE_PV   2

// ---------------------------------------------------------------------------
__device__ __forceinline__ uint32_t smem_u32(const void* p) {
    uint32_t a;
    asm("{ .reg .u64 t; cvta.to.shared.u64 t, %1; cvt.u32.u64 %0, t; }"
        : "=r"(a) : "l"(p));
    return a;
}

__device__ __forceinline__ void cp16(uint32_t dst, const void* src) {
    asm volatile("cp.async.cg.shared.global [%0], [%1], 16;"
                 :: "r"(dst), "l"(src));
}
#define CP_COMMIT() asm volatile("cp.async.commit_group;" ::: "memory")
#define CP_WAIT1()  asm volatile("cp.async.wait_group 1;" ::: "memory")

__device__ __forceinline__ void ldsm4(uint32_t r[4], uint32_t addr) {
    asm volatile("ldmatrix.sync.aligned.m8n8.x4.shared.b16 {%0,%1,%2,%3}, [%4];"
                 : "=r"(r[0]), "=r"(r[1]), "=r"(r[2]), "=r"(r[3]) : "r"(addr));
}

__device__ __forceinline__ void mma_f16(float c[4], const uint32_t a[4],
                                        uint32_t b0, uint32_t b1) {
    asm volatile(
        "mma.sync.aligned.m16n8k16.row.col.f32.f16.f16.f32 "
        "{%0,%1,%2,%3}, {%4,%5,%6,%7}, {%8,%9}, {%0,%1,%2,%3};"
        : "+f"(c[0]), "+f"(c[1]), "+f"(c[2]), "+f"(c[3])
        : "r"(a[0]), "r"(a[1]), "r"(a[2]), "r"(a[3]), "r"(b0), "r"(b1));
}

// Issue one k-stage's cp.async loads (A: 4/thread, B: 8/thread).
__device__ __forceinline__ void issue_stage(const __half* __restrict__ Ag, int lda,
                                            const __half* __restrict__ Bg, int ldb,
                                            uint32_t sm, int ks, int buf, int tid) {
    const __half* a = Ag + (size_t)ks * BK;
    const uint32_t ab = sm + buf * STAGE_BYTES;
    #pragma unroll
    for (int t = 0; t < 4; t++) {
        int idx = tid + t * NTH;
        int row = idx >> 3, ch = idx & 7;
        cp16(ab + swz(row, ch), a + (size_t)row * lda + (ch << 3));
    }
    const __half* b = Bg + (size_t)ks * BK;
    const uint32_t bb = ab + A_BUF;
    #pragma unroll
    for (int t = 0; t < 8; t++) {
        int idx = tid + t * NTH;
        int row = idx >> 3, ch = idx & 7;
        cp16(bb + swz(row, ch), b + (size_t)row * ldb + (ch << 3));
    }
}

// ---------------------------------------------------------------------------
// Core: C[128x256] = A[128 x nk*64] @ B^T; fp16 K-major operands in gmem.
// ---------------------------------------------------------------------------
template <int MODE>
__device__ __forceinline__ void gemm_core(const __half* __restrict__ Ag, int lda,
                                          const __half* __restrict__ Bg, int ldb,
                                          void* __restrict__ Cg, int ldc,
                                          int nk, float scale,
                                          int gr0, int gc0,
                                          float* __restrict__ psum,
                                          const float* __restrict__ rinv,
                                          char* smem) {
    const uint32_t sm = smem_u32(smem);
    const int tid = threadIdx.x, lane = tid & 31, warp = tid >> 5;
    const int warpM = warp >> 2, warpN = warp & 3;
    const int l15 = lane & 15, lh = lane >> 4;

    float c[4][8][4] = {};

    issue_stage(Ag, lda, Bg, ldb, sm, 0, 0, tid);
    CP_COMMIT();
    issue_stage(Ag, lda, Bg, ldb, sm, 1, 1, tid);
    CP_COMMIT();

    for (int i = 0; i < nk; i++) {
        CP_WAIT1();              // stage i resident
        __syncthreads();         // all warps past compute(i-1); buf (i+2)%3 free
        if (i + 2 < nk)
            issue_stage(Ag, lda, Bg, ldb, sm, i + 2, (i + 2) % STAGES, tid);
        CP_COMMIT();             // unconditional: keeps group count exact
        const uint32_t abase = sm + (i % STAGES) * STAGE_BYTES;
        const uint32_t bbase = abase + A_BUF;
        #pragma unroll
        for (int s = 0; s < 4; s++) {
            uint32_t afr[4][4];
            #pragma unroll
            for (int mt = 0; mt < 4; mt++)
                ldsm4(afr[mt], abase + swz(warpM * 64 + mt * 16 + l15, 2 * s + lh));
            uint32_t bfr[4][4];
            #pragma unroll
            for (int np = 0; np < 4; np++)
                ldsm4(bfr[np], bbase + swz(warpN * 64 + np * 16 + l15, 2 * s + lh));
            #pragma unroll
            for (int mt = 0; mt < 4; mt++)
                #pragma unroll
                for (int np = 0; np < 4; np++) {
                    mma_f16(c[mt][2 * np], afr[mt], bfr[np][0], bfr[np][2]);
                    mma_f16(c[mt][2 * np + 1], afr[mt], bfr[np][1], bfr[np][3]);
                }
        }
    }

    // Epilogue
    #pragma unroll
    for (int mt = 0; mt < 4; mt++) {
        const int rl0 = warpM * 64 + mt * 16 + (lane >> 2);
        float rs0 = 0.0f, rs1 = 0.0f;
        float inv0 = 1.0f, inv1 = 1.0f;
        if (MODE == MODE_PV) {
            inv0 = rinv[rl0];
            inv1 = rinv[rl0 + 8];
        }
        #pragma unroll
        for (int nt = 0; nt < 8; nt++) {
            const int cl = warpN * 64 + nt * 8 + (lane & 3) * 2;
            float v0 = c[mt][nt][0], v1 = c[mt][nt][1];
            float v2 = c[mt][nt][2], v3 = c[mt][nt][3];
            if (MODE == MODE_HALF) {
                __half* C = reinterpret_cast<__half*>(Cg);
                *reinterpret_cast<__half2*>(&C[(size_t)rl0 * ldc + cl]) =
                    __floats2half2_rn(v0, v1);
                *reinterpret_cast<__half2*>(&C[(size_t)(rl0 + 8) * ldc + cl]) =
                    __floats2half2_rn(v2, v3);
            } else if (MODE == MODE_EXP) {
                const int gc = gc0 + cl;
                const int r0 = gr0 + rl0, r1 = r0 + 8;
                float e0 = (gc     <= r0) ? __expf(v0 * scale) : 0.0f;
                float e1 = (gc + 1 <= r0) ? __expf(v1 * scale) : 0.0f;
                float e2 = (gc     <= r1) ? __expf(v2 * scale) : 0.0f;
                float e3 = (gc + 1 <= r1) ? __expf(v3 * scale) : 0.0f;
                rs0 += e0 + e1;
                rs1 += e2 + e3;
                __half* C = reinterpret_cast<__half*>(Cg);
                *reinterpret_cast<__half2*>(&C[(size_t)rl0 * ldc + cl]) =
                    __floats2half2_rn(e0, e1);
                *reinterpret_cast<__half2*>(&C[(size_t)(rl0 + 8) * ldc + cl]) =
                    __floats2half2_rn(e2, e3);
            } else {
                float* C = reinterpret_cast<float*>(Cg);
                *reinterpret_cast<float2*>(&C[(size_t)rl0 * ldc + cl]) =
                    make_float2(v0 * inv0, v1 * inv0);
                *reinterpret_cast<float2*>(&C[(size_t)(rl0 + 8) * ldc + cl]) =
                    make_float2(v2 * inv1, v3 * inv1);
            }
        }
        if (MODE == MODE_EXP) {
            #pragma unroll
            for (int o = 1; o < 4; o <<= 1) {
                rs0 += __shfl_xor_sync(~0u, rs0, o);
                rs1 += __shfl_xor_sync(~0u, rs1, o);
            }
            if ((lane & 3) == 0) {
                psum[(size_t)rl0 * 32 + warpN] = rs0;
                psum[(size_t)(rl0 + 8) * 32 + warpN] = rs1;
            }
        }
    }
}

// ---------------------------------------------------------------------------
// GEMM kernels (heavy-first by-remap on scores/pv)
// ---------------------------------------------------------------------------
__global__ __launch_bounds__(NTH)
void mm_qkv() {
    extern __shared__ char smem[];
    const int which = blockIdx.z;
    const int row0 = blockIdx.y * BM, col0 = blockIdx.x * BN;
    const __half* A = g_xh + (size_t)row0 * DIM;
    const __half* B = g_wth + (size_t)which * DIM * DIM + (size_t)col0 * DIM;
    __half* C = ((which == 0) ? g_qh : (which == 1) ? g_kh : g_vh) +
                (size_t)row0 * DIM + col0;
    gemm_core<MODE_HALF>(A, DIM, B, DIM, C, DIM, DIM / BK, 1.0f,
                         0, 0, nullptr, nullptr, smem);
}

__global__ __launch_bounds__(NTH)
void mm_scores(float scale) {
    const int bx = blockIdx.x;
    const int by = (gridDim.y - 1) - blockIdx.y;   // heavy tiles first
    if (2 * bx > by) return;                        // fully-masked key tile
    extern __shared__ char smem[];
    const int b = blockIdx.z;
    const int row0 = by * BM, col0 = bx * BN;
    const __half* A = g_qh + (size_t)b * SEQ * DIM + (size_t)row0 * DIM;
    const __half* B = g_kh + (size_t)b * SEQ * DIM + (size_t)col0 * DIM;
    __half* C = g_ph + (size_t)b * SEQ * SEQ + (size_t)row0 * SEQ + col0;
    float* psum = g_psum + (size_t)(b * SEQ + row0) * 32 + bx * 4;
    gemm_core<MODE_EXP>(A, DIM, B, DIM, C, SEQ, DIM / BK, scale,
                        row0, col0, psum, nullptr, smem);
}

__global__ __launch_bounds__(NTH)
void mm_pv(float* __restrict__ out) {
    extern __shared__ char smem[];
    const int b = blockIdx.z;
    const int by = (gridDim.y - 1) - blockIdx.y;   // heavy tiles first
    const int row0 = by * BM, col0 = blockIdx.x * BN;
    const __half* A = g_ph + (size_t)b * SEQ * SEQ + (size_t)row0 * SEQ;
    const __half* B = g_vth + (size_t)b * DIM * SEQ + (size_t)col0 * SEQ;
    float* C = out + (size_t)b * SEQ * DIM + (size_t)row0 * DIM + col0;
    const float* rinv = g_rinv + (size_t)b * SEQ + row0;
    gemm_core<MODE_PV>(A, SEQ, B, SEQ, C, DIM, 2 * (by + 1), 1.0f,
                       0, 0, nullptr, rinv, smem);
}

// ---------------------------------------------------------------------------
// Row-sum finalize (deterministic, no atomics)
// ---------------------------------------------------------------------------
__global__ __launch_bounds__(NTH)
void reduce_rinv() {
    const int row = blockIdx.x * NTH + threadIdx.x;
    const int q = row & (SEQ - 1);
    const int nw = ((q >> 8) + 1) * 4;
    const float* p = g_psum + (size_t)row * 32;
    float s = 0.0f;
    for (int j = 0; j < nw; j++) s += p[j];
    g_rinv[row] = 1.0f / s;
}

// ---------------------------------------------------------------------------
// Prep kernels
// ---------------------------------------------------------------------------
__global__ void round_x(const float* __restrict__ x) {
    size_t i = (size_t)(blockIdx.x * blockDim.x + threadIdx.x) * 4;
    float4 v = *reinterpret_cast<const float4*>(x + i);
    *reinterpret_cast<__half2*>(g_xh + i) = __floats2half2_rn(v.x, v.y);
    *reinterpret_cast<__half2*>(g_xh + i + 2) = __floats2half2_rn(v.z, v.w);
}

__global__ void tr_w(const float* __restrict__ Wq, const float* __restrict__ Wk,
                     const float* __restrict__ Wv) {
    __shared__ float t[32][33];
    const int z = blockIdx.z;
    const float* S = (z == 0) ? Wq : (z == 1) ? Wk : Wv;
    __half* D = g_wth + (size_t)z * DIM * DIM;
    const int x0 = blockIdx.x * 32, y0 = blockIdx.y * 32;
    const int tx = threadIdx.x, ty = threadIdx.y;
    #pragma unroll
    for (int j = 0; j < 32; j += 8)
        t[ty + j][tx] = S[(size_t)(y0 + ty + j) * DIM + x0 + tx];
    __syncthreads();
    #pragma unroll
    for (int j = 0; j < 32; j += 8)
        D[(size_t)(x0 + ty + j) * DIM + y0 + tx] = __float2half_rn(t[tx][ty + j]);
}

__global__ void tr_v() {
    __shared__ __half t[32][40];
    const int b = blockIdx.z;
    const __half* S = g_vh + (size_t)b * SEQ * DIM;
    __half* D = g_vth + (size_t)b * DIM * SEQ;
    const int x0 = blockIdx.x * 32, y0 = blockIdx.y * 32;
    const int tx = threadIdx.x, ty = threadIdx.y;
    #pragma unroll
    for (int j = 0; j < 32; j += 8)
        t[ty + j][tx] = S[(size_t)(y0 + ty + j) * DIM + x0 + tx];
    __syncthreads();
    #pragma unroll
    for (int j = 0; j < 32; j += 8)
        D[(size_t)(x0 + ty + j) * SEQ + y0 + tx] = t[tx][ty + j];
}

// ---------------------------------------------------------------------------
extern "C" void kernel_launch(void* const* d_in, const int* in_sizes, int n_in,
                              void* d_out, int out_size) {
    const float* x  = (const float*)d_in[0];
    const float* Wq = (const float*)d_in[1];
    const float* Wk = (const float*)d_in[2];
    const float* Wv = (const float*)d_in[3];
    float* out = (float*)d_out;

    cudaFuncSetAttribute(mm_qkv, cudaFuncAttributeMaxDynamicSharedMemorySize, SMEM_TOTAL);
    cudaFuncSetAttribute(mm_scores, cudaFuncAttributeMaxDynamicSharedMemorySize, SMEM_TOTAL);
    cudaFuncSetAttribute(mm_pv, cudaFuncAttributeMaxDynamicSharedMemorySize, SMEM_TOTAL);

    // 1) x -> fp16, W^T -> fp16
    round_x<<<(MROWS * DIM) / (4 * NTH), NTH>>>(x);
    tr_w<<<dim3(32, 32, 3), dim3(32, 8)>>>(Wq, Wk, Wv);
    // 2) QKV projections
    mm_qkv<<<dim3(DIM / BN, MROWS / BM, 3), NTH, SMEM_TOTAL>>>();
    // 3) V^T
    tr_v<<<dim3(DIM / 32, SEQ / 32, BATCH), dim3(32, 8)>>>();
    // 4) exp(scores) + partial sums (lower-triangular tiles, heavy-first)
    const float scale = 1.0f / sqrtf((float)DIM);
    mm_scores<<<dim3(SEQ / BN, SEQ / BM, BATCH), NTH, SMEM_TOTAL>>>(scale);
    // 5) finalize 1/rowsum
    reduce_rinv<<<MROWS / NTH, NTH>>>();
    // 6) out = (P V) * rinv (heavy-first)
    mm_pv<<<dim3(DIM / BN, SEQ / BM, BATCH), NTH, SMEM_TOTAL>>>(out);
}

// round 11
// speedup vs baseline: 3.1519x; 1.0124x over previous
#include <cuda_runtime.h>
#include <cuda_fp16.h>
#include <math.h>
#include <stdint.h>

#define BATCH 4
#define SEQ   2048
#define DIM   1024
#define MROWS (BATCH * SEQ)

// Scratch (__device__ globals). GEMM inputs in fp16 (rounded at producer).
__device__ __half g_xh[MROWS * DIM];
__device__ __half g_qh[BATCH * SEQ * DIM];
__device__ __half g_kh[BATCH * SEQ * DIM];
__device__ __half g_vh[BATCH * SEQ * DIM];
__device__ __half g_vth[BATCH * DIM * SEQ];          // V^T [dim][seq]
__device__ __half g_wth[3 * DIM * DIM];              // W^T [n][k]
__device__ __half g_ph[(size_t)BATCH * SEQ * SEQ];   // unnormalized exp(score)
__device__ float  g_psum[(size_t)MROWS * 32];        // partial row sums
__device__ float  g_rinv[MROWS];                     // 1 / row sum

// GEMM config: CTA 128x256xBK64 (halves); 8 warps 2(M)x4(N); warp tile 64x64.
// 3-stage cp.async pipeline, 48 KB per stage, 144 KB total.
#define BM 128
#define BN 256
#define BK 64
#define NTH 256
#define STAGES 3
#define A_BUF 16384
#define B_BUF 32768
#define STAGE_BYTES (A_BUF + B_BUF)
#define SMEM_TOTAL (STAGES * STAGE_BYTES)  // 147456

// Row = 64 halves = 128 B = 8 x 16B chunks. addr = row*128 + (c ^ (row&7))*16.
__device__ __forceinline__ uint32_t swz(int row, int chunk) {
    return ((uint32_t)row << 7) + ((uint32_t)(chunk ^ (row & 7)) << 4);
}

// Epilogue modes
#define MODE_HALF 0
#define MODE_EXP  1
#define MODE_PV   2

// ---------------------------------------------------------------------------
__device__ __forceinline__ uint32_t smem_u32(const void* p) {
    uint32_t a;
    asm("{ .reg .u64 t; cvta.to.shared.u64 t, %1; cvt.u32.u64 %0, t; }"
        : "=r"(a) : "l"(p));
    return a;
}

__device__ __forceinline__ void cp16(uint32_t dst, const void* src) {
    asm volatile("cp.async.cg.shared.global [%0], [%1], 16;"
                 :: "r"(dst), "l"(src));
}
#define CP_COMMIT() asm volatile("cp.async.commit_group;" ::: "memory")
#define CP_WAIT1()  asm volatile("cp.async.wait_group 1;" ::: "memory")

__device__ __forceinline__ void ldsm4(uint32_t r[4], uint32_t addr) {
    asm volatile("ldmatrix.sync.aligned.m8n8.x4.shared.b16 {%0,%1,%2,%3}, [%4];"
                 : "=r"(r[0]), "=r"(r[1]), "=r"(r[2]), "=r"(r[3]) : "r"(addr));
}

__device__ __forceinline__ void mma_f16(float c[4], const uint32_t a[4],
                                        uint32_t b0, uint32_t b1) {
    asm volatile(
        "mma.sync.aligned.m16n8k16.row.col.f32.f16.f16.f32 "
        "{%0,%1,%2,%3}, {%4,%5,%6,%7}, {%8,%9}, {%0,%1,%2,%3};"
        : "+f"(c[0]), "+f"(c[1]), "+f"(c[2]), "+f"(c[3])
        : "r"(a[0]), "r"(a[1]), "r"(a[2]), "r"(a[3]), "r"(b0), "r"(b1));
}

// Issue one k-stage's cp.async loads (A: 4/thread, B: 8/thread).
__device__ __forceinline__ void issue_stage(const __half* __restrict__ Ag, int lda,
                                            const __half* __restrict__ Bg, int ldb,
                                            uint32_t sm, int ks, int buf, int tid) {
    const __half* a = Ag + (size_t)ks * BK;
    const uint32_t ab = sm + buf * STAGE_BYTES;
    #pragma unroll
    for (int t = 0; t < 4; t++) {
        int idx = tid + t * NTH;
        int row = idx >> 3, ch = idx & 7;
        cp16(ab + swz(row, ch), a + (size_t)row * lda + (ch << 3));
    }
    const __half* b = Bg + (size_t)ks * BK;
    const uint32_t bb = ab + A_BUF;
    #pragma unroll
    for (int t = 0; t < 8; t++) {
        int idx = tid + t * NTH;
        int row = idx >> 3, ch = idx & 7;
        cp16(bb + swz(row, ch), b + (size_t)row * ldb + (ch << 3));
    }
}

// Load one s-step's fragments (8 ldmatrix.x4).
__device__ __forceinline__ void load_frag(uint32_t afr[4][4], uint32_t bfr[4][4],
                                          uint32_t abase, uint32_t bbase,
                                          int s, int warpM, int warpN,
                                          int l15, int lh) {
    #pragma unroll
    for (int mt = 0; mt < 4; mt++)
        ldsm4(afr[mt], abase + swz(warpM * 64 + mt * 16 + l15, 2 * s + lh));
    #pragma unroll
    for (int np = 0; np < 4; np++)
        ldsm4(bfr[np], bbase + swz(warpN * 64 + np * 16 + l15, 2 * s + lh));
}

__device__ __forceinline__ void do_mma(float c[4][8][4], uint32_t afr[4][4],
                                       uint32_t bfr[4][4]) {
    #pragma unroll
    for (int mt = 0; mt < 4; mt++)
        #pragma unroll
        for (int np = 0; np < 4; np++) {
            mma_f16(c[mt][2 * np], afr[mt], bfr[np][0], bfr[np][2]);
            mma_f16(c[mt][2 * np + 1], afr[mt], bfr[np][1], bfr[np][3]);
        }
}

// ---------------------------------------------------------------------------
// Core: C[128x256] = A[128 x nk*64] @ B^T; fp16 K-major operands in gmem.
// cp.async 3-stage + fragment double-buffering across s-steps.
// ---------------------------------------------------------------------------
template <int MODE>
__device__ __forceinline__ void gemm_core(const __half* __restrict__ Ag, int lda,
                                          const __half* __restrict__ Bg, int ldb,
                                          void* __restrict__ Cg, int ldc,
                                          int nk, float scale,
                                          int gr0, int gc0,
                                          float* __restrict__ psum,
                                          const float* __restrict__ rinv,
                                          char* smem) {
    const uint32_t sm = smem_u32(smem);
    const int tid = threadIdx.x, lane = tid & 31, warp = tid >> 5;
    const int warpM = warp >> 2, warpN = warp & 3;
    const int l15 = lane & 15, lh = lane >> 4;

    float c[4][8][4] = {};
    uint32_t afr[2][4][4], bfr[2][4][4];

    issue_stage(Ag, lda, Bg, ldb, sm, 0, 0, tid);
    CP_COMMIT();
    issue_stage(Ag, lda, Bg, ldb, sm, 1, 1, tid);
    CP_COMMIT();

    for (int i = 0; i < nk; i++) {
        CP_WAIT1();
        __syncthreads();
        if (i + 2 < nk)
            issue_stage(Ag, lda, Bg, ldb, sm, i + 2, (i + 2) % STAGES, tid);
        CP_COMMIT();
        const uint32_t abase = sm + (i % STAGES) * STAGE_BYTES;
        const uint32_t bbase = abase + A_BUF;
        load_frag(afr[0], bfr[0], abase, bbase, 0, warpM, warpN, l15, lh);
        #pragma unroll
        for (int s = 0; s < 4; s++) {
            const int cur = s & 1;
            if (s < 3)
                load_frag(afr[cur ^ 1], bfr[cur ^ 1], abase, bbase, s + 1,
                          warpM, warpN, l15, lh);
            do_mma(c, afr[cur], bfr[cur]);
        }
    }

    // Epilogue
    #pragma unroll
    for (int mt = 0; mt < 4; mt++) {
        const int rl0 = warpM * 64 + mt * 16 + (lane >> 2);
        float rs0 = 0.0f, rs1 = 0.0f;
        float inv0 = 1.0f, inv1 = 1.0f;
        if (MODE == MODE_PV) {
            inv0 = rinv[rl0];
            inv1 = rinv[rl0 + 8];
        }
        #pragma unroll
        for (int nt = 0; nt < 8; nt++) {
            const int cl = warpN * 64 + nt * 8 + (lane & 3) * 2;
            float v0 = c[mt][nt][0], v1 = c[mt][nt][1];
            float v2 = c[mt][nt][2], v3 = c[mt][nt][3];
            if (MODE == MODE_HALF) {
                __half* C = reinterpret_cast<__half*>(Cg);
                *reinterpret_cast<__half2*>(&C[(size_t)rl0 * ldc + cl]) =
                    __floats2half2_rn(v0, v1);
                *reinterpret_cast<__half2*>(&C[(size_t)(rl0 + 8) * ldc + cl]) =
                    __floats2half2_rn(v2, v3);
            } else if (MODE == MODE_EXP) {
                const int gc = gc0 + cl;
                const int r0 = gr0 + rl0, r1 = r0 + 8;
                float e0 = (gc     <= r0) ? __expf(v0 * scale) : 0.0f;
                float e1 = (gc + 1 <= r0) ? __expf(v1 * scale) : 0.0f;
                float e2 = (gc     <= r1) ? __expf(v2 * scale) : 0.0f;
                float e3 = (gc + 1 <= r1) ? __expf(v3 * scale) : 0.0f;
                rs0 += e0 + e1;
                rs1 += e2 + e3;
                __half* C = reinterpret_cast<__half*>(Cg);
                *reinterpret_cast<__half2*>(&C[(size_t)rl0 * ldc + cl]) =
                    __floats2half2_rn(e0, e1);
                *reinterpret_cast<__half2*>(&C[(size_t)(rl0 + 8) * ldc + cl]) =
                    __floats2half2_rn(e2, e3);
            } else {
                float* C = reinterpret_cast<float*>(Cg);
                *reinterpret_cast<float2*>(&C[(size_t)rl0 * ldc + cl]) =
                    make_float2(v0 * inv0, v1 * inv0);
                *reinterpret_cast<float2*>(&C[(size_t)(rl0 + 8) * ldc + cl]) =
                    make_float2(v2 * inv1, v3 * inv1);
            }
        }
        if (MODE == MODE_EXP) {
            #pragma unroll
            for (int o = 1; o < 4; o <<= 1) {
                rs0 += __shfl_xor_sync(~0u, rs0, o);
                rs1 += __shfl_xor_sync(~0u, rs1, o);
            }
            if ((lane & 3) == 0) {
                psum[(size_t)rl0 * 32 + warpN] = rs0;
                psum[(size_t)(rl0 + 8) * 32 + warpN] = rs1;
            }
        }
    }
}

// ---------------------------------------------------------------------------
// GEMM kernels (heavy-first by-remap on scores/pv)
// ---------------------------------------------------------------------------
__global__ __launch_bounds__(NTH)
void mm_qkv() {
    extern __shared__ char smem[];
    const int which = blockIdx.z;
    const int row0 = blockIdx.y * BM, col0 = blockIdx.x * BN;
    const __half* A = g_xh + (size_t)row0 * DIM;
    const __half* B = g_wth + (size_t)which * DIM * DIM + (size_t)col0 * DIM;
    __half* C = ((which == 0) ? g_qh : (which == 1) ? g_kh : g_vh) +
                (size_t)row0 * DIM + col0;
    gemm_core<MODE_HALF>(A, DIM, B, DIM, C, DIM, DIM / BK, 1.0f,
                         0, 0, nullptr, nullptr, smem);
}

__global__ __launch_bounds__(NTH)
void mm_scores(float scale) {
    const int bx = blockIdx.x;
    const int by = (gridDim.y - 1) - blockIdx.y;   // heavy tiles first
    if (2 * bx > by) return;                        // fully-masked key tile
    extern __shared__ char smem[];
    const int b = blockIdx.z;
    const int row0 = by * BM, col0 = bx * BN;
    const __half* A = g_qh + (size_t)b * SEQ * DIM + (size_t)row0 * DIM;
    const __half* B = g_kh + (size_t)b * SEQ * DIM + (size_t)col0 * DIM;
    __half* C = g_ph + (size_t)b * SEQ * SEQ + (size_t)row0 * SEQ + col0;
    float* psum = g_psum + (size_t)(b * SEQ + row0) * 32 + bx * 4;
    gemm_core<MODE_EXP>(A, DIM, B, DIM, C, SEQ, DIM / BK, scale,
                        row0, col0, psum, nullptr, smem);
}

__global__ __launch_bounds__(NTH)
void mm_pv(float* __restrict__ out) {
    extern __shared__ char smem[];
    const int b = blockIdx.z;
    const int by = (gridDim.y - 1) - blockIdx.y;   // heavy tiles first
    const int row0 = by * BM, col0 = blockIdx.x * BN;
    const __half* A = g_ph + (size_t)b * SEQ * SEQ + (size_t)row0 * SEQ;
    const __half* B = g_vth + (size_t)b * DIM * SEQ + (size_t)col0 * SEQ;
    float* C = out + (size_t)b * SEQ * DIM + (size_t)row0 * DIM + col0;
    const float* rinv = g_rinv + (size_t)b * SEQ + row0;
    gemm_core<MODE_PV>(A, SEQ, B, SEQ, C, DIM, 2 * (by + 1), 1.0f,
                       0, 0, nullptr, rinv, smem);
}

// ---------------------------------------------------------------------------
// Row-sum finalize (deterministic, no atomics)
// ---------------------------------------------------------------------------
__global__ __launch_bounds__(NTH)
void reduce_rinv() {
    const int row = blockIdx.x * NTH + threadIdx.x;
    const int q = row & (SEQ - 1);
    const int nw = ((q >> 8) + 1) * 4;
    const float* p = g_psum + (size_t)row * 32;
    float s = 0.0f;
    for (int j = 0; j < nw; j++) s += p[j];
    g_rinv[row] = 1.0f / s;
}

// ---------------------------------------------------------------------------
// Prep kernels
// ---------------------------------------------------------------------------
__global__ void round_x(const float* __restrict__ x) {
    size_t i = (size_t)(blockIdx.x * blockDim.x + threadIdx.x) * 4;
    float4 v = *reinterpret_cast<const float4*>(x + i);
    *reinterpret_cast<__half2*>(g_xh + i) = __floats2half2_rn(v.x, v.y);
    *reinterpret_cast<__half2*>(g_xh + i + 2) = __floats2half2_rn(v.z, v.w);
}

__global__ void tr_w(const float* __restrict__ Wq, const float* __restrict__ Wk,
                     const float* __restrict__ Wv) {
    __shared__ float t[32][33];
    const int z = blockIdx.z;
    const float* S = (z == 0) ? Wq : (z == 1) ? Wk : Wv;
    __half* D = g_wth + (size_t)z * DIM * DIM;
    const int x0 = blockIdx.x * 32, y0 = blockIdx.y * 32;
    const int tx = threadIdx.x, ty = threadIdx.y;
    #pragma unroll
    for (int j = 0; j < 32; j += 8)
        t[ty + j][tx] = S[(size_t)(y0 + ty + j) * DIM + x0 + tx];
    __syncthreads();
    #pragma unroll
    for (int j = 0; j < 32; j += 8)
        D[(size_t)(x0 + ty + j) * DIM + y0 + tx] = __float2half_rn(t[tx][ty + j]);
}

__global__ void tr_v() {
    __shared__ __half t[32][40];
    const int b = blockIdx.z;
    const __half* S = g_vh + (size_t)b * SEQ * DIM;
    __half* D = g_vth + (size_t)b * DIM * SEQ;
    const int x0 = blockIdx.x * 32, y0 = blockIdx.y * 32;
    const int tx = threadIdx.x, ty = threadIdx.y;
    #pragma unroll
    for (int j = 0; j < 32; j += 8)
        t[ty + j][tx] = S[(size_t)(y0 + ty + j) * DIM + x0 + tx];
    __syncthreads();
    #pragma unroll
    for (int j = 0; j < 32; j += 8)
        D[(size_t)(x0 + ty + j) * SEQ + y0 + tx] = t[tx][ty + j];
}

// ---------------------------------------------------------------------------
extern "C" void kernel_launch(void* const* d_in, const int* in_sizes, int n_in,
                              void* d_out, int out_size) {
    const float* x  = (const float*)d_in[0];
    const float* Wq = (const float*)d_in[1];
    const float* Wk = (const float*)d_in[2];
    const float* Wv = (const float*)d_in[3];
    float* out = (float*)d_out;

    cudaFuncSetAttribute(mm_qkv, cudaFuncAttributeMaxDynamicSharedMemorySize, SMEM_TOTAL);
    cudaFuncSetAttribute(mm_scores, cudaFuncAttributeMaxDynamicSharedMemorySize, SMEM_TOTAL);
    cudaFuncSetAttribute(mm_pv, cudaFuncAttributeMaxDynamicSharedMemorySize, SMEM_TOTAL);

    round_x<<<(MROWS * DIM) / (4 * NTH), NTH>>>(x);
    tr_w<<<dim3(32, 32, 3), dim3(32, 8)>>>(Wq, Wk, Wv);
    mm_qkv<<<dim3(DIM / BN, MROWS / BM, 3), NTH, SMEM_TOTAL>>>();
    tr_v<<<dim3(DIM / 32, SEQ / 32, BATCH), dim3(32, 8)>>>();
    const float scale = 1.0f / sqrtf((float)DIM);
    mm_scores<<<dim3(SEQ / BN, SEQ / BM, BATCH), NTH, SMEM_TOTAL>>>(scale);
    reduce_rinv<<<MROWS / NTH, NTH>>>();
    mm_pv<<<dim3(DIM / BN, SEQ / BM, BATCH), NTH, SMEM_TOTAL>>>(out);
}